// round 6
// baseline (speedup 1.0000x reference)
#include <cuda_runtime.h>
#include <math.h>

// ---------------- problem constants ----------------
#define T_TOK 16384          // 4 * 4096 tokens
#define DM    1024           // d_model
#define HID   512            // hidden
#define NE    16             // experts
#define TOPK  2

// ---------------- tiling ----------------
#define BM 64
#define BN 64
#define BK 16
#define MAX_TILES 528                 // sum ceil(c_e/64) <= 32768/64 + 16
#define PAD_ROWS  (MAX_TILES * BM)    // 33792

// ---------------- static scratch (no allocation allowed) ----------------
__device__ int   g_counts[NE];
__device__ int   g_cursor[NE];
__device__ int   g_off[NE];
__device__ int   g_tile_e[MAX_TILES];
__device__ int   g_tile_base[MAX_TILES];
__device__ int   g_tok_idx[T_TOK * TOPK];
__device__ float g_tok_w[T_TOK * TOPK];
__device__ int   g_row_tok[PAD_ROWS];
__device__ float g_row_w[PAD_ROWS];
__device__ __align__(16) float g_H[(size_t)PAD_ROWS * HID];   // ~69 MB

// ---------------- kernels ----------------
__global__ void init_kernel() {
    int i = threadIdx.x;
    if (i < NE) g_counts[i] = 0;
}

// one warp per token: logits -> softmax -> top-2 -> normalized weights
__global__ void gate_kernel(const float* __restrict__ x,
                            const float* __restrict__ gw,
                            const float* __restrict__ gb) {
    int gid  = blockIdx.x * blockDim.x + threadIdx.x;
    int t    = gid >> 5;
    int lane = gid & 31;
    if (t >= T_TOK) return;

    const float* xr = x + (size_t)t * DM;
    float acc[NE];
#pragma unroll
    for (int e = 0; e < NE; e++) acc[e] = 0.f;

    for (int d = lane; d < DM; d += 32) {
        float xv = xr[d];
        const float* g = gw + d * NE;
#pragma unroll
        for (int e = 0; e < NE; e++) acc[e] = fmaf(xv, g[e], acc[e]);
    }
#pragma unroll
    for (int e = 0; e < NE; e++) {
#pragma unroll
        for (int o = 16; o > 0; o >>= 1)
            acc[e] += __shfl_xor_sync(0xffffffffu, acc[e], o);
    }
    if (lane == 0) {
        float s[NE];
        float mx = -1e30f;
#pragma unroll
        for (int e = 0; e < NE; e++) { s[e] = acc[e] + gb[e]; mx = fmaxf(mx, s[e]); }
        float sum = 0.f;
#pragma unroll
        for (int e = 0; e < NE; e++) { s[e] = expf(s[e] - mx); sum += s[e]; }
        // top-2 (strict > : lowest index wins ties, matching lax.top_k)
        int i1 = 0; float v1 = -1.f;
#pragma unroll
        for (int e = 0; e < NE; e++) if (s[e] > v1) { v1 = s[e]; i1 = e; }
        int i2 = 0; float v2 = -1.f;
#pragma unroll
        for (int e = 0; e < NE; e++) if (e != i1 && s[e] > v2) { v2 = s[e]; i2 = e; }
        float p1 = v1 / sum, p2 = v2 / sum;
        float den = p1 + p2 + 1e-9f;
        float w1 = p1 / den, w2 = p2 / den;
        g_tok_idx[2 * t + 0] = i1; g_tok_w[2 * t + 0] = w1;
        g_tok_idx[2 * t + 1] = i2; g_tok_w[2 * t + 1] = w2;
        atomicAdd(&g_counts[i1], 1);
        atomicAdd(&g_counts[i2], 1);
    }
}

// serial but tiny: padded offsets, tile tables, padding rows
__global__ void scan_kernel() {
    int off = 0, tile = 0;
    for (int e = 0; e < NE; e++) {
        g_off[e] = off;
        g_cursor[e] = 0;
        int c  = g_counts[e];
        int nt = (c + BM - 1) / BM;
        for (int j = 0; j < nt; j++) {
            g_tile_e[tile]    = e;
            g_tile_base[tile] = off + j * BM;
            tile++;
        }
        for (int r = off + c; r < off + nt * BM; r++) {
            g_row_tok[r] = -1;
            g_row_w[r]   = 0.f;
        }
        off += nt * BM;
    }
    for (; tile < MAX_TILES; tile++) g_tile_e[tile] = -1;
}

__global__ void scatter_kernel() {
    int t = blockIdx.x * blockDim.x + threadIdx.x;
    if (t >= T_TOK) return;
#pragma unroll
    for (int k = 0; k < TOPK; k++) {
        int   e = g_tok_idx[2 * t + k];
        float w = g_tok_w[2 * t + k];
        int pos = g_off[e] + atomicAdd(&g_cursor[e], 1);
        g_row_tok[pos] = t;
        g_row_w[pos]   = w;
    }
}

__global__ void zero_kernel(float* out, long n) {
    long i      = blockIdx.x * (long)blockDim.x + threadIdx.x;
    long stride = (long)gridDim.x * blockDim.x;
    for (; i < n; i += stride) out[i] = 0.f;
}

__global__ void aux_kernel(float* out, long out_size) {
    if (blockIdx.x == 0 && threadIdx.x == 0) {
        const float cap = 1.25f * (float)(T_TOK * TOPK) / (float)NE;  // 2560
        float sum = 0.f;
        for (int e = 0; e < NE; e++) {
            float l = (float)g_counts[e] - cap;
            if (l > 0.f) sum += l;
        }
        float aux = 0.01f * sum / (float)NE / (float)T_TOK;
        long TD = (long)T_TOK * DM;
        if (out_size > TD) out[TD] = aux;
    }
}

// FFN stage 1: H[r, n] = (x_r @ gp + gp_b) * silu(x_r @ up + up_b)
// fused gp/up GEMM per block: BMxBN tile, K = DM
__global__ void __launch_bounds__(256)
ffn1_kernel(const float* __restrict__ x,
            const float* __restrict__ gp_w, const float* __restrict__ gp_b,
            const float* __restrict__ up_w, const float* __restrict__ up_b) {
    int mt = blockIdx.y;
    int e  = g_tile_e[mt];
    if (e < 0) return;
    int rb = g_tile_base[mt];
    int n0 = blockIdx.x * BN;   // [0, 512)

    __shared__ float As[BK][BM];
    __shared__ float Bg[BK][BN];
    __shared__ float Bu[BK][BN];
    __shared__ int   toks[BM];

    int tid = threadIdx.x;
    if (tid < BM) toks[tid] = g_row_tok[rb + tid];
    __syncthreads();

    int lm  = tid >> 2;         // 0..63 : A row
    int lk  = (tid & 3) * 4;    // A k offset (float4)
    int lkb = tid >> 4;         // 0..15 : B k row
    int lnb = (tid & 15) * 4;   // B n offset (float4)
    int tx  = tid & 15, ty = tid >> 4;

    const float* gpw = gp_w + (size_t)e * DM * HID;
    const float* upw = up_w + (size_t)e * DM * HID;
    int mytok = toks[lm];
    const float* arow = (mytok >= 0) ? (x + (size_t)mytok * DM) : nullptr;

    float ag[4][4] = {}, au[4][4] = {};

    for (int k0 = 0; k0 < DM; k0 += BK) {
        float4 av  = arow ? *(const float4*)(arow + k0 + lk)
                          : make_float4(0.f, 0.f, 0.f, 0.f);
        float4 bgv = *(const float4*)(gpw + (size_t)(k0 + lkb) * HID + n0 + lnb);
        float4 buv = *(const float4*)(upw + (size_t)(k0 + lkb) * HID + n0 + lnb);
        __syncthreads();
        As[lk + 0][lm] = av.x; As[lk + 1][lm] = av.y;
        As[lk + 2][lm] = av.z; As[lk + 3][lm] = av.w;
        *(float4*)&Bg[lkb][lnb] = bgv;
        *(float4*)&Bu[lkb][lnb] = buv;
        __syncthreads();
#pragma unroll
        for (int kk = 0; kk < BK; kk++) {
            float4 a4 = *(const float4*)&As[kk][ty * 4];
            float4 g4 = *(const float4*)&Bg[kk][tx * 4];
            float4 u4 = *(const float4*)&Bu[kk][tx * 4];
            float aa[4] = {a4.x, a4.y, a4.z, a4.w};
            float gg[4] = {g4.x, g4.y, g4.z, g4.w};
            float uu[4] = {u4.x, u4.y, u4.z, u4.w};
#pragma unroll
            for (int i = 0; i < 4; i++)
#pragma unroll
                for (int j = 0; j < 4; j++) {
                    ag[i][j] = fmaf(aa[i], gg[j], ag[i][j]);
                    au[i][j] = fmaf(aa[i], uu[j], au[i][j]);
                }
        }
    }

    const float* gpb = gp_b + e * HID;
    const float* upb = up_b + e * HID;
#pragma unroll
    for (int i = 0; i < 4; i++) {
        int r = rb + ty * 4 + i;
        float4 hv;
        float* h = &hv.x;
#pragma unroll
        for (int j = 0; j < 4; j++) {
            int n = n0 + tx * 4 + j;
            float g = ag[i][j] + gpb[n];
            float u = au[i][j] + upb[n];
            float su = u / (1.f + expf(-u));
            h[j] = g * su;
        }
        *(float4*)(g_H + (size_t)r * HID + n0 + tx * 4) = hv;
    }
}

// FFN stage 2: out[tok] += w * (H_r @ dp_w[e] + dp_b[e]), K = HID
__global__ void __launch_bounds__(256)
ffn2_kernel(const float* __restrict__ dp_w,
            const float* __restrict__ dp_b,
            float* __restrict__ out) {
    int mt = blockIdx.y;
    int e  = g_tile_e[mt];
    if (e < 0) return;
    int rb = g_tile_base[mt];
    int n0 = blockIdx.x * BN;   // [0, 1024)

    __shared__ float As[BK][BM];
    __shared__ float Bs[BK][BN];
    __shared__ int   toks[BM];
    __shared__ float wts[BM];

    int tid = threadIdx.x;
    if (tid < BM) { toks[tid] = g_row_tok[rb + tid]; wts[tid] = g_row_w[rb + tid]; }

    int lm  = tid >> 2;
    int lk  = (tid & 3) * 4;
    int lkb = tid >> 4;
    int lnb = (tid & 15) * 4;
    int tx  = tid & 15, ty = tid >> 4;

    const float* dw   = dp_w + (size_t)e * HID * DM;
    const float* arow = g_H + (size_t)(rb + lm) * HID;

    float ac[4][4] = {};

    for (int k0 = 0; k0 < HID; k0 += BK) {
        float4 av = *(const float4*)(arow + k0 + lk);
        float4 bv = *(const float4*)(dw + (size_t)(k0 + lkb) * DM + n0 + lnb);
        __syncthreads();
        As[lk + 0][lm] = av.x; As[lk + 1][lm] = av.y;
        As[lk + 2][lm] = av.z; As[lk + 3][lm] = av.w;
        *(float4*)&Bs[lkb][lnb] = bv;
        __syncthreads();
#pragma unroll
        for (int kk = 0; kk < BK; kk++) {
            float4 a4 = *(const float4*)&As[kk][ty * 4];
            float4 b4 = *(const float4*)&Bs[kk][tx * 4];
            float aa[4] = {a4.x, a4.y, a4.z, a4.w};
            float bb[4] = {b4.x, b4.y, b4.z, b4.w};
#pragma unroll
            for (int i = 0; i < 4; i++)
#pragma unroll
                for (int j = 0; j < 4; j++)
                    ac[i][j] = fmaf(aa[i], bb[j], ac[i][j]);
        }
    }

    const float* dpb = dp_b + e * DM;
#pragma unroll
    for (int i = 0; i < 4; i++) {
        int tok = toks[ty * 4 + i];
        if (tok < 0) continue;
        float w = wts[ty * 4 + i];
        float* orow = out + (size_t)tok * DM;
#pragma unroll
        for (int j = 0; j < 4; j++) {
            int n = n0 + tx * 4 + j;
            atomicAdd(orow + n, w * (ac[i][j] + dpb[n]));
        }
    }
}

// ---------------- launcher ----------------
extern "C" void kernel_launch(void* const* d_in, const int* in_sizes, int n_in,
                              void* d_out, int out_size) {
    const float* x   = (const float*)d_in[0];
    const float* gw  = (const float*)d_in[1];
    const float* gb  = (const float*)d_in[2];
    const float* gpw = (const float*)d_in[3];
    const float* gpb = (const float*)d_in[4];
    const float* upw = (const float*)d_in[5];
    const float* upb = (const float*)d_in[6];
    const float* dpw = (const float*)d_in[7];
    const float* dpb = (const float*)d_in[8];
    float* out = (float*)d_out;

    init_kernel<<<1, 32>>>();
    gate_kernel<<<(T_TOK * 32 + 255) / 256, 256>>>(x, gw, gb);
    scan_kernel<<<1, 1>>>();
    scatter_kernel<<<(T_TOK + 255) / 256, 256>>>();
    zero_kernel<<<2048, 256>>>(out, (long)out_size);
    aux_kernel<<<1, 32>>>(out, (long)out_size);

    dim3 gA(HID / BN, MAX_TILES);
    ffn1_kernel<<<gA, 256>>>(x, gpw, gpb, upw, upb);
    dim3 gB(DM / BN, MAX_TILES);
    ffn2_kernel<<<gB, 256>>>(dpw, dpb, out);
}

// round 8
// speedup vs baseline: 1.9137x; 1.9137x over previous
#include <cuda_runtime.h>
#include <math.h>
#include <stdint.h>

// ---------------- problem constants ----------------
#define T_TOK 16384
#define DM    1024
#define HID   512
#define NE    16
#define TOPK  2

// ---------------- tiling ----------------
#define BMT 128
#define BNT 128
#define MTILES 272                   // sum ceil(c_e/128) <= 32768/128 + 16
#define PAD_ROWS (MTILES * BMT)
#define TW 2176                      // words per smem tile: 16 k-rows * 136 stride

// ---------------- static scratch ----------------
__device__ int   g_counts[NE];
__device__ int   g_cursor[NE];
__device__ int   g_off[NE];
__device__ int   g_tile_e[MTILES];
__device__ int   g_tile_base[MTILES];
__device__ int   g_tok_idx[T_TOK * TOPK];
__device__ float g_tok_w[T_TOK * TOPK];
__device__ int   g_tok_pos[T_TOK * TOPK];
__device__ int   g_row_tok[PAD_ROWS];
__device__ __align__(16) float g_H[(size_t)PAD_ROWS * HID];
__device__ __align__(16) float g_Y[(size_t)PAD_ROWS * DM];

// ---------------- helpers ----------------
__device__ __forceinline__ uint32_t f2tf(float f) {
    uint32_t r;
    asm("cvt.rna.tf32.f32 %0, %1;" : "=r"(r) : "f"(f));
    return r;
}

__device__ __forceinline__ void mma8(float c[4], const uint32_t a[4],
                                     uint32_t b0, uint32_t b1) {
    asm volatile(
        "mma.sync.aligned.m16n8k8.row.col.f32.tf32.tf32.f32 "
        "{%0,%1,%2,%3}, {%4,%5,%6,%7}, {%8,%9}, {%0,%1,%2,%3};"
        : "+f"(c[0]), "+f"(c[1]), "+f"(c[2]), "+f"(c[3])
        : "r"(a[0]), "r"(a[1]), "r"(a[2]), "r"(a[3]), "r"(b0), "r"(b1));
}

// ---------------- routing kernels ----------------
__global__ void init_kernel() {
    int i = threadIdx.x;
    if (i < NE) g_counts[i] = 0;
}

__global__ void gate_kernel(const float* __restrict__ x,
                            const float* __restrict__ gw,
                            const float* __restrict__ gb) {
    int gid = blockIdx.x * blockDim.x + threadIdx.x;
    int t = gid >> 5, lane = gid & 31;
    if (t >= T_TOK) return;
    const float* xr = x + (size_t)t * DM;
    float acc[NE];
#pragma unroll
    for (int e = 0; e < NE; e++) acc[e] = 0.f;
    for (int d = lane; d < DM; d += 32) {
        float xv = xr[d];
        const float* g = gw + d * NE;
#pragma unroll
        for (int e = 0; e < NE; e++) acc[e] = fmaf(xv, g[e], acc[e]);
    }
#pragma unroll
    for (int e = 0; e < NE; e++)
#pragma unroll
        for (int o = 16; o > 0; o >>= 1)
            acc[e] += __shfl_xor_sync(0xffffffffu, acc[e], o);
    if (lane == 0) {
        float s[NE], mx = -1e30f;
#pragma unroll
        for (int e = 0; e < NE; e++) { s[e] = acc[e] + gb[e]; mx = fmaxf(mx, s[e]); }
        float sum = 0.f;
#pragma unroll
        for (int e = 0; e < NE; e++) { s[e] = expf(s[e] - mx); sum += s[e]; }
        int i1 = 0; float v1 = -1.f;
#pragma unroll
        for (int e = 0; e < NE; e++) if (s[e] > v1) { v1 = s[e]; i1 = e; }
        int i2 = 0; float v2 = -1.f;
#pragma unroll
        for (int e = 0; e < NE; e++) if (e != i1 && s[e] > v2) { v2 = s[e]; i2 = e; }
        float p1 = v1 / sum, p2 = v2 / sum;
        float den = p1 + p2 + 1e-9f;
        g_tok_idx[2 * t + 0] = i1; g_tok_w[2 * t + 0] = p1 / den;
        g_tok_idx[2 * t + 1] = i2; g_tok_w[2 * t + 1] = p2 / den;
        atomicAdd(&g_counts[i1], 1);
        atomicAdd(&g_counts[i2], 1);
    }
}

__global__ void scan_kernel() {
    int off = 0, tile = 0;
    for (int e = 0; e < NE; e++) {
        g_off[e] = off; g_cursor[e] = 0;
        int c = g_counts[e];
        int nt = (c + BMT - 1) / BMT;
        for (int j = 0; j < nt; j++) {
            g_tile_e[tile] = e;
            g_tile_base[tile] = off + j * BMT;
            tile++;
        }
        for (int r = off + c; r < off + nt * BMT; r++) g_row_tok[r] = -1;
        off += nt * BMT;
    }
    for (; tile < MTILES; tile++) g_tile_e[tile] = -1;
}

__global__ void scatter_kernel() {
    int t = blockIdx.x * blockDim.x + threadIdx.x;
    if (t >= T_TOK) return;
#pragma unroll
    for (int k = 0; k < TOPK; k++) {
        int e = g_tok_idx[2 * t + k];
        int pos = g_off[e] + atomicAdd(&g_cursor[e], 1);
        g_row_tok[pos] = t;
        g_tok_pos[2 * t + k] = pos;
    }
}

__global__ void zero_kernel(float* out, long n) {
    long i = blockIdx.x * (long)blockDim.x + threadIdx.x;
    long st = (long)gridDim.x * blockDim.x;
    for (; i < n; i += st) out[i] = 0.f;
}

__global__ void aux_kernel(float* out, long out_size) {
    if (blockIdx.x == 0 && threadIdx.x == 0) {
        const float cap = 1.25f * (float)(T_TOK * TOPK) / (float)NE;
        float sum = 0.f;
        for (int e = 0; e < NE; e++) {
            float l = (float)g_counts[e] - cap;
            if (l > 0.f) sum += l;
        }
        float aux = 0.01f * sum / (float)NE / (float)T_TOK;
        long TD = (long)T_TOK * DM;
        if (out_size > TD) out[TD] = aux;
    }
}

// ============ FFN stage 1: H = (X@gp + b) * silu(X@up + b), tf32 mma ============
// SMEM layout per stage: A[k][m] stride 136, Bg[k][n], Bu[k][n] stride 136.
__global__ void __launch_bounds__(256)
ffn1_mma(const float* __restrict__ x,
         const float* __restrict__ gp_w, const float* __restrict__ up_w,
         const float* __restrict__ gp_b, const float* __restrict__ up_b) {
    int mt = blockIdx.x;
    int e = g_tile_e[mt];
    if (e < 0) return;
    int rb = g_tile_base[mt];
    int n0 = blockIdx.y * BNT;

    extern __shared__ uint32_t sm[];    // 2 stages * 3 tiles * TW
    __shared__ int s_toks[BMT];

    int tid = threadIdx.x, lane = tid & 31, wid = tid >> 5;
    if (tid < BMT) s_toks[tid] = g_row_tok[rb + tid];
    __syncthreads();

    // ---- loader mapping (2 float4 per tile per thread) ----
    const float* ap[2]; int a_m[2], a_k4[2];
    const float* bgp[2]; const float* bup[2]; int b_k[2], b_n4[2];
    const float* gpe = gp_w + (size_t)e * DM * HID;
    const float* upe = up_w + (size_t)e * DM * HID;
#pragma unroll
    for (int j = 0; j < 2; j++) {
        int pos = tid + 256 * j;
        a_m[j] = pos >> 2; a_k4[j] = pos & 3;
        int tok = s_toks[a_m[j]];
        ap[j] = (tok >= 0) ? x + (size_t)tok * DM + a_k4[j] * 4 : (const float*)0;
        b_k[j] = pos >> 5; b_n4[j] = pos & 31;
        bgp[j] = gpe + (size_t)b_k[j] * HID + n0 + b_n4[j] * 4;
        bup[j] = upe + (size_t)b_k[j] * HID + n0 + b_n4[j] * 4;
    }

    float cg[2][8][4] = {}, cu[2][8][4] = {};
    int mb = (wid & 3) * 32 + (lane >> 2);
    int nb = (wid >> 2) * 64 + (lane >> 2);
    int kl = lane & 3;

    float4 va[2], vg[2], vu[2];
    // prefetch chunk 0
#pragma unroll
    for (int j = 0; j < 2; j++) {
        va[j] = ap[j] ? *(const float4*)(ap[j]) : make_float4(0.f, 0.f, 0.f, 0.f);
        vg[j] = *(const float4*)(bgp[j]);
        vu[j] = *(const float4*)(bup[j]);
    }
    // store stage 0
    {
        uint32_t* A = sm; uint32_t* G = sm + TW; uint32_t* U = sm + 2 * TW;
#pragma unroll
        for (int j = 0; j < 2; j++) {
            float av[4] = {va[j].x, va[j].y, va[j].z, va[j].w};
            float gv[4] = {vg[j].x, vg[j].y, vg[j].z, vg[j].w};
            float uv[4] = {vu[j].x, vu[j].y, vu[j].z, vu[j].w};
#pragma unroll
            for (int i = 0; i < 4; i++) {
                int ii = (i + a_k4[j]) & 3;
                A[(4 * a_k4[j] + ii) * 136 + a_m[j]] = f2tf(av[ii]);
            }
            int rot = b_n4[j] >> 3;
#pragma unroll
            for (int i = 0; i < 4; i++) {
                int ii = (i + rot) & 3;
                G[b_k[j] * 136 + 4 * b_n4[j] + ii] = f2tf(gv[ii]);
                U[b_k[j] * 136 + 4 * b_n4[j] + ii] = f2tf(uv[ii]);
            }
        }
    }
    __syncthreads();

    const int NC = DM / 16;   // 64
    for (int c = 0; c < NC; ++c) {
        if (c + 1 < NC) {
            size_t ka = (size_t)(c + 1) * 16;
            size_t kb = (size_t)(c + 1) * 16 * HID;
#pragma unroll
            for (int j = 0; j < 2; j++) {
                va[j] = ap[j] ? *(const float4*)(ap[j] + ka) : make_float4(0.f, 0.f, 0.f, 0.f);
                vg[j] = *(const float4*)(bgp[j] + kb);
                vu[j] = *(const float4*)(bup[j] + kb);
            }
        }
        // compute current stage
        {
            const uint32_t* A = sm + (c & 1) * 3 * TW;
            const uint32_t* G = A + TW;
            const uint32_t* U = A + 2 * TW;
#pragma unroll
            for (int s = 0; s < 2; s++) {
                int k0 = 8 * s + kl;
                uint32_t a[2][4];
#pragma unroll
                for (int mi = 0; mi < 2; mi++) {
                    int m = mb + mi * 16;
                    a[mi][0] = A[k0 * 136 + m];
                    a[mi][1] = A[k0 * 136 + m + 8];
                    a[mi][2] = A[(k0 + 4) * 136 + m];
                    a[mi][3] = A[(k0 + 4) * 136 + m + 8];
                }
#pragma unroll
                for (int ni = 0; ni < 8; ni++) {
                    int n = nb + ni * 8;
                    uint32_t g0 = G[k0 * 136 + n], g1 = G[(k0 + 4) * 136 + n];
                    uint32_t u0 = U[k0 * 136 + n], u1 = U[(k0 + 4) * 136 + n];
                    mma8(cg[0][ni], a[0], g0, g1);
                    mma8(cg[1][ni], a[1], g0, g1);
                    mma8(cu[0][ni], a[0], u0, u1);
                    mma8(cu[1][ni], a[1], u0, u1);
                }
            }
        }
        if (c + 1 < NC) {
            uint32_t* A = sm + ((c + 1) & 1) * 3 * TW;
            uint32_t* G = A + TW;
            uint32_t* U = A + 2 * TW;
#pragma unroll
            for (int j = 0; j < 2; j++) {
                float av[4] = {va[j].x, va[j].y, va[j].z, va[j].w};
                float gv[4] = {vg[j].x, vg[j].y, vg[j].z, vg[j].w};
                float uv[4] = {vu[j].x, vu[j].y, vu[j].z, vu[j].w};
#pragma unroll
                for (int i = 0; i < 4; i++) {
                    int ii = (i + a_k4[j]) & 3;
                    A[(4 * a_k4[j] + ii) * 136 + a_m[j]] = f2tf(av[ii]);
                }
                int rot = b_n4[j] >> 3;
#pragma unroll
                for (int i = 0; i < 4; i++) {
                    int ii = (i + rot) & 3;
                    G[b_k[j] * 136 + 4 * b_n4[j] + ii] = f2tf(gv[ii]);
                    U[b_k[j] * 136 + 4 * b_n4[j] + ii] = f2tf(uv[ii]);
                }
            }
            __syncthreads();
        }
    }

    // ---- epilogue: silu fuse -> g_H ----
    const float* gpb = gp_b + e * HID + n0;
    const float* upb = up_b + e * HID + n0;
    int rrow = rb + (wid & 3) * 32 + (lane >> 2);
    int cbase = (wid >> 2) * 64 + 2 * (lane & 3);
#pragma unroll
    for (int ni = 0; ni < 8; ni++) {
        int col = cbase + ni * 8;
        float gb0 = gpb[col], gb1 = gpb[col + 1];
        float ub0 = upb[col], ub1 = upb[col + 1];
#pragma unroll
        for (int mi = 0; mi < 2; mi++) {
            int r0 = rrow + mi * 16;
            float g, u;
            float2 h;
            g = cg[mi][ni][0] + gb0; u = cu[mi][ni][0] + ub0;
            h.x = g * (u / (1.f + expf(-u)));
            g = cg[mi][ni][1] + gb1; u = cu[mi][ni][1] + ub1;
            h.y = g * (u / (1.f + expf(-u)));
            *(float2*)(g_H + (size_t)r0 * HID + n0 + col) = h;
            g = cg[mi][ni][2] + gb0; u = cu[mi][ni][2] + ub0;
            h.x = g * (u / (1.f + expf(-u)));
            g = cg[mi][ni][3] + gb1; u = cu[mi][ni][3] + ub1;
            h.y = g * (u / (1.f + expf(-u)));
            *(float2*)(g_H + (size_t)(r0 + 8) * HID + n0 + col) = h;
        }
    }
}

// ============ FFN stage 2: Y = H @ dp_w, tf32 mma ============
__global__ void __launch_bounds__(256)
ffn2_mma(const float* __restrict__ dp_w) {
    int mt = blockIdx.x;
    int e = g_tile_e[mt];
    if (e < 0) return;
    int rb = g_tile_base[mt];
    int n0 = blockIdx.y * BNT;   // over DM

    __shared__ uint32_t sm2[2 * 2 * TW];

    int tid = threadIdx.x, lane = tid & 31, wid = tid >> 5;

    const float* ap[2]; int a_m[2], a_k4[2];
    const float* bp[2]; int b_k[2], b_n4[2];
    const float* dpe = dp_w + (size_t)e * HID * DM;
#pragma unroll
    for (int j = 0; j < 2; j++) {
        int pos = tid + 256 * j;
        a_m[j] = pos >> 2; a_k4[j] = pos & 3;
        ap[j] = g_H + (size_t)(rb + a_m[j]) * HID + a_k4[j] * 4;
        b_k[j] = pos >> 5; b_n4[j] = pos & 31;
        bp[j] = dpe + (size_t)b_k[j] * DM + n0 + b_n4[j] * 4;
    }

    float ca[2][8][4] = {};
    int mb = (wid & 3) * 32 + (lane >> 2);
    int nb = (wid >> 2) * 64 + (lane >> 2);
    int kl = lane & 3;

    float4 va[2], vb[2];
#pragma unroll
    for (int j = 0; j < 2; j++) {
        va[j] = *(const float4*)(ap[j]);
        vb[j] = *(const float4*)(bp[j]);
    }
    {
        uint32_t* A = sm2; uint32_t* B = sm2 + TW;
#pragma unroll
        for (int j = 0; j < 2; j++) {
            float av[4] = {va[j].x, va[j].y, va[j].z, va[j].w};
            float bv[4] = {vb[j].x, vb[j].y, vb[j].z, vb[j].w};
#pragma unroll
            for (int i = 0; i < 4; i++) {
                int ii = (i + a_k4[j]) & 3;
                A[(4 * a_k4[j] + ii) * 136 + a_m[j]] = f2tf(av[ii]);
            }
            int rot = b_n4[j] >> 3;
#pragma unroll
            for (int i = 0; i < 4; i++) {
                int ii = (i + rot) & 3;
                B[b_k[j] * 136 + 4 * b_n4[j] + ii] = f2tf(bv[ii]);
            }
        }
    }
    __syncthreads();

    const int NC = HID / 16;   // 32
    for (int c = 0; c < NC; ++c) {
        if (c + 1 < NC) {
            size_t ka = (size_t)(c + 1) * 16;
            size_t kb = (size_t)(c + 1) * 16 * DM;
#pragma unroll
            for (int j = 0; j < 2; j++) {
                va[j] = *(const float4*)(ap[j] + ka);
                vb[j] = *(const float4*)(bp[j] + kb);
            }
        }
        {
            const uint32_t* A = sm2 + (c & 1) * 2 * TW;
            const uint32_t* B = A + TW;
#pragma unroll
            for (int s = 0; s < 2; s++) {
                int k0 = 8 * s + kl;
                uint32_t a[2][4];
#pragma unroll
                for (int mi = 0; mi < 2; mi++) {
                    int m = mb + mi * 16;
                    a[mi][0] = A[k0 * 136 + m];
                    a[mi][1] = A[k0 * 136 + m + 8];
                    a[mi][2] = A[(k0 + 4) * 136 + m];
                    a[mi][3] = A[(k0 + 4) * 136 + m + 8];
                }
#pragma unroll
                for (int ni = 0; ni < 8; ni++) {
                    int n = nb + ni * 8;
                    uint32_t b0 = B[k0 * 136 + n], b1 = B[(k0 + 4) * 136 + n];
                    mma8(ca[0][ni], a[0], b0, b1);
                    mma8(ca[1][ni], a[1], b0, b1);
                }
            }
        }
        if (c + 1 < NC) {
            uint32_t* A = sm2 + ((c + 1) & 1) * 2 * TW;
            uint32_t* B = A + TW;
#pragma unroll
            for (int j = 0; j < 2; j++) {
                float av[4] = {va[j].x, va[j].y, va[j].z, va[j].w};
                float bv[4] = {vb[j].x, vb[j].y, vb[j].z, vb[j].w};
#pragma unroll
                for (int i = 0; i < 4; i++) {
                    int ii = (i + a_k4[j]) & 3;
                    A[(4 * a_k4[j] + ii) * 136 + a_m[j]] = f2tf(av[ii]);
                }
                int rot = b_n4[j] >> 3;
#pragma unroll
                for (int i = 0; i < 4; i++) {
                    int ii = (i + rot) & 3;
                    B[b_k[j] * 136 + 4 * b_n4[j] + ii] = f2tf(bv[ii]);
                }
            }
            __syncthreads();
        }
    }

    int rrow = rb + (wid & 3) * 32 + (lane >> 2);
    int cbase = (wid >> 2) * 64 + 2 * (lane & 3);
#pragma unroll
    for (int ni = 0; ni < 8; ni++) {
        int col = n0 + cbase + ni * 8;
#pragma unroll
        for (int mi = 0; mi < 2; mi++) {
            int r0 = rrow + mi * 16;
            float2 v0 = make_float2(ca[mi][ni][0], ca[mi][ni][1]);
            float2 v1 = make_float2(ca[mi][ni][2], ca[mi][ni][3]);
            *(float2*)(g_Y + (size_t)r0 * DM + col) = v0;
            *(float2*)(g_Y + (size_t)(r0 + 8) * DM + col) = v1;
        }
    }
}

// combine: out[t] = w1*(Y[p1]+b_e1) + w2*(Y[p2]+b_e2)
__global__ void __launch_bounds__(256)
combine_kernel(const float* __restrict__ dp_b, float* __restrict__ out) {
    int t = blockIdx.x;
    int c = threadIdx.x;   // float4 index, DM/4 = 256
    int e1 = g_tok_idx[2 * t], e2 = g_tok_idx[2 * t + 1];
    float w1 = g_tok_w[2 * t], w2 = g_tok_w[2 * t + 1];
    int p1 = g_tok_pos[2 * t], p2 = g_tok_pos[2 * t + 1];
    float4 y1 = ((const float4*)(g_Y + (size_t)p1 * DM))[c];
    float4 y2 = ((const float4*)(g_Y + (size_t)p2 * DM))[c];
    float4 b1 = ((const float4*)(dp_b + (size_t)e1 * DM))[c];
    float4 b2 = ((const float4*)(dp_b + (size_t)e2 * DM))[c];
    float4 r;
    r.x = w1 * (y1.x + b1.x) + w2 * (y2.x + b2.x);
    r.y = w1 * (y1.y + b1.y) + w2 * (y2.y + b2.y);
    r.z = w1 * (y1.z + b1.z) + w2 * (y2.z + b2.z);
    r.w = w1 * (y1.w + b1.w) + w2 * (y2.w + b2.w);
    ((float4*)out)[(size_t)t * (DM / 4) + c] = r;
}

// ---------------- launcher ----------------
#define FFN1_SMEM (2 * 3 * TW * 4)   // 52224 bytes

extern "C" void kernel_launch(void* const* d_in, const int* in_sizes, int n_in,
                              void* d_out, int out_size) {
    const float* x   = (const float*)d_in[0];
    const float* gw  = (const float*)d_in[1];
    const float* gb  = (const float*)d_in[2];
    const float* gpw = (const float*)d_in[3];
    const float* gpb = (const float*)d_in[4];
    const float* upw = (const float*)d_in[5];
    const float* upb = (const float*)d_in[6];
    const float* dpw = (const float*)d_in[7];
    const float* dpb = (const float*)d_in[8];
    float* out = (float*)d_out;

    static int attr_done = 0;
    if (!attr_done) {
        cudaFuncSetAttribute(ffn1_mma, cudaFuncAttributeMaxDynamicSharedMemorySize,
                             FFN1_SMEM);
        attr_done = 1;
    }

    init_kernel<<<1, 32>>>();
    gate_kernel<<<(T_TOK * 32 + 255) / 256, 256>>>(x, gw, gb);
    scan_kernel<<<1, 1>>>();
    scatter_kernel<<<(T_TOK + 255) / 256, 256>>>();
    zero_kernel<<<1024, 256>>>(out, (long)out_size);
    aux_kernel<<<1, 32>>>(out, (long)out_size);

    ffn1_mma<<<dim3(MTILES, HID / BNT), 256, FFN1_SMEM>>>(x, gpw, upw, gpb, upb);
    ffn2_mma<<<dim3(MTILES, DM / BNT), 256>>>(dpw);
    combine_kernel<<<T_TOK, 256>>>(dpb, out);
}

// round 9
// speedup vs baseline: 2.2998x; 1.2018x over previous
#include <cuda_runtime.h>
#include <math.h>
#include <stdint.h>

// ---------------- problem constants ----------------
#define T_TOK 16384
#define DM    1024
#define HID   512
#define NE    16
#define TOPK  2

// ---------------- tiling ----------------
#define BMT 128
#define BNT 128
#define BK  16
#define MTILES 272
#define PAD_ROWS (MTILES * BMT)

#define A_STRIDE 20                    // words per A row (16 + 4 pad) -> conflict-free
#define B_STRIDE 136                   // words per B k-row (128 + 8 pad)
#define A_WORDS (128 * A_STRIDE)       // 2560
#define B_WORDS (BK * B_STRIDE)        // 2176
#define F1_STAGE (A_WORDS + 2 * B_WORDS)   // 6912 words
#define F1_SMEM  (2 * F1_STAGE * 4)        // 55296 bytes
#define F2_STAGE (A_WORDS + B_WORDS)       // 4736 words

// ---------------- static scratch ----------------
__device__ int   g_counts[NE];
__device__ int   g_cursor[NE];
__device__ int   g_off[NE];
__device__ int   g_tile_e[MTILES];
__device__ int   g_tile_base[MTILES];
__device__ int   g_tok_idx[T_TOK * TOPK];
__device__ float g_tok_w[T_TOK * TOPK];
__device__ int   g_tok_pos[T_TOK * TOPK];
__device__ int   g_row_tok[PAD_ROWS];
__device__ __align__(16) float g_Xr[(size_t)T_TOK * DM];        // tf32-rounded x
__device__ __align__(16) float g_gpr[(size_t)NE * DM * HID];
__device__ __align__(16) float g_upr[(size_t)NE * DM * HID];
__device__ __align__(16) float g_dpr[(size_t)NE * HID * DM];
__device__ __align__(16) float g_H[(size_t)PAD_ROWS * HID];
__device__ __align__(16) float g_Y[(size_t)PAD_ROWS * DM];

// ---------------- helpers ----------------
__device__ __forceinline__ uint32_t smem_u32(const void* p) {
    uint32_t a;
    asm("{ .reg .u64 t; cvta.to.shared.u64 t, %1; cvt.u32.u64 %0, t; }" : "=r"(a) : "l"(p));
    return a;
}

__device__ __forceinline__ float f2tf(float f) {
    uint32_t r;
    asm("cvt.rna.tf32.f32 %0, %1;" : "=r"(r) : "f"(f));
    return __uint_as_float(r);
}

__device__ __forceinline__ void mma8(float c[4], const uint32_t a[4],
                                     uint32_t b0, uint32_t b1) {
    asm volatile(
        "mma.sync.aligned.m16n8k8.row.col.f32.tf32.tf32.f32 "
        "{%0,%1,%2,%3}, {%4,%5,%6,%7}, {%8,%9}, {%0,%1,%2,%3};"
        : "+f"(c[0]), "+f"(c[1]), "+f"(c[2]), "+f"(c[3])
        : "r"(a[0]), "r"(a[1]), "r"(a[2]), "r"(a[3]), "r"(b0), "r"(b1));
}

#define CP16(dst, src) \
    asm volatile("cp.async.cg.shared.global [%0], [%1], 16;" :: "r"(dst), "l"(src))
#define CP16Z(dst, src, sz) \
    asm volatile("cp.async.cg.shared.global [%0], [%1], 16, %2;" :: "r"(dst), "l"(src), "r"(sz))
#define CP_COMMIT() asm volatile("cp.async.commit_group;" ::: "memory")
#define CP_WAIT0()  asm volatile("cp.async.wait_group 0;" ::: "memory")

// ---------------- routing kernels ----------------
__global__ void init_kernel() {
    int i = threadIdx.x;
    if (i < NE) g_counts[i] = 0;
}

__global__ void gate_kernel(const float* __restrict__ x,
                            const float* __restrict__ gw,
                            const float* __restrict__ gb) {
    int gid = blockIdx.x * blockDim.x + threadIdx.x;
    int t = gid >> 5, lane = gid & 31;
    if (t >= T_TOK) return;
    const float* xr = x + (size_t)t * DM;
    float acc[NE];
#pragma unroll
    for (int e = 0; e < NE; e++) acc[e] = 0.f;
    for (int d = lane; d < DM; d += 32) {
        float xv = xr[d];
        const float* g = gw + d * NE;
#pragma unroll
        for (int e = 0; e < NE; e++) acc[e] = fmaf(xv, g[e], acc[e]);
    }
#pragma unroll
    for (int e = 0; e < NE; e++)
#pragma unroll
        for (int o = 16; o > 0; o >>= 1)
            acc[e] += __shfl_xor_sync(0xffffffffu, acc[e], o);
    if (lane == 0) {
        float s[NE], mx = -1e30f;
#pragma unroll
        for (int e = 0; e < NE; e++) { s[e] = acc[e] + gb[e]; mx = fmaxf(mx, s[e]); }
        float sum = 0.f;
#pragma unroll
        for (int e = 0; e < NE; e++) { s[e] = expf(s[e] - mx); sum += s[e]; }
        int i1 = 0; float v1 = -1.f;
#pragma unroll
        for (int e = 0; e < NE; e++) if (s[e] > v1) { v1 = s[e]; i1 = e; }
        int i2 = 0; float v2 = -1.f;
#pragma unroll
        for (int e = 0; e < NE; e++) if (e != i1 && s[e] > v2) { v2 = s[e]; i2 = e; }
        float p1 = v1 / sum, p2 = v2 / sum;
        float den = p1 + p2 + 1e-9f;
        g_tok_idx[2 * t + 0] = i1; g_tok_w[2 * t + 0] = p1 / den;
        g_tok_idx[2 * t + 1] = i2; g_tok_w[2 * t + 1] = p2 / den;
        atomicAdd(&g_counts[i1], 1);
        atomicAdd(&g_counts[i2], 1);
    }
}

__global__ void scan_kernel() {
    int off = 0, tile = 0;
    for (int e = 0; e < NE; e++) {
        g_off[e] = off; g_cursor[e] = 0;
        int c = g_counts[e];
        int nt = (c + BMT - 1) / BMT;
        for (int j = 0; j < nt; j++) {
            g_tile_e[tile] = e;
            g_tile_base[tile] = off + j * BMT;
            tile++;
        }
        for (int r = off + c; r < off + nt * BMT; r++) g_row_tok[r] = -1;
        off += nt * BMT;
    }
    for (; tile < MTILES; tile++) g_tile_e[tile] = -1;
}

__global__ void scatter_kernel() {
    int t = blockIdx.x * blockDim.x + threadIdx.x;
    if (t >= T_TOK) return;
#pragma unroll
    for (int k = 0; k < TOPK; k++) {
        int e = g_tok_idx[2 * t + k];
        int pos = g_off[e] + atomicAdd(&g_cursor[e], 1);
        g_row_tok[pos] = t;
        g_tok_pos[2 * t + k] = pos;
    }
}

__global__ void aux_kernel(float* out, long out_size) {
    if (blockIdx.x == 0 && threadIdx.x == 0) {
        const float cap = 1.25f * (float)(T_TOK * TOPK) / (float)NE;
        float sum = 0.f;
        for (int e = 0; e < NE; e++) {
            float l = (float)g_counts[e] - cap;
            if (l > 0.f) sum += l;
        }
        float aux = 0.01f * sum / (float)NE / (float)T_TOK;
        long TD = (long)T_TOK * DM;
        if (out_size > TD) out[TD] = aux;
    }
}

// round x / gp / up / dp to tf32 once (elementwise, float4)
__global__ void round_all(const float* __restrict__ x,
                          const float* __restrict__ gp,
                          const float* __restrict__ up,
                          const float* __restrict__ dp) {
    const long NX = (long)T_TOK * DM / 4;
    const long NW = (long)NE * DM * HID / 4;
    long i = blockIdx.x * (long)blockDim.x + threadIdx.x;
    long st = (long)gridDim.x * blockDim.x;
    long total = NX + 3 * NW;
    for (; i < total; i += st) {
        const float4* s; float4* d; long j;
        if (i < NX)               { s = (const float4*)x;  d = (float4*)g_Xr;  j = i; }
        else if (i < NX + NW)     { s = (const float4*)gp; d = (float4*)g_gpr; j = i - NX; }
        else if (i < NX + 2 * NW) { s = (const float4*)up; d = (float4*)g_upr; j = i - NX - NW; }
        else                      { s = (const float4*)dp; d = (float4*)g_dpr; j = i - NX - 2 * NW; }
        float4 v = s[j];
        v.x = f2tf(v.x); v.y = f2tf(v.y); v.z = f2tf(v.z); v.w = f2tf(v.w);
        d[j] = v;
    }
}

// ============ FFN stage 1: H = (X@gp + b) * silu(X@up + b) ============
__global__ void __launch_bounds__(256)
ffn1_mma(const float* __restrict__ gp_b, const float* __restrict__ up_b) {
    int mt = blockIdx.x;
    int e = g_tile_e[mt];
    if (e < 0) return;
    int rb = g_tile_base[mt];
    int n0 = blockIdx.y * BNT;

    extern __shared__ uint32_t sm[];
    __shared__ int s_toks[BMT];

    int tid = threadIdx.x, lane = tid & 31, wid = tid >> 5;
    if (tid < BMT) s_toks[tid] = g_row_tok[rb + tid];
    __syncthreads();

    uint32_t sbase = smem_u32(sm);
    const float* gpe = g_gpr + (size_t)e * DM * HID + n0;
    const float* upe = g_upr + (size_t)e * DM * HID + n0;

    // loader mapping: 2 pieces per tile per thread
    const float* asrc[2]; uint32_t asz[2], adst[2];
    const float* gsrc[2]; const float* usrc[2]; uint32_t bdst[2];
#pragma unroll
    for (int j = 0; j < 2; j++) {
        int p = tid + 256 * j;
        int row = p >> 2, pc = p & 3;
        int tok = s_toks[row];
        asrc[j] = g_Xr + (size_t)(tok >= 0 ? tok : 0) * DM + pc * 4;
        asz[j]  = (tok >= 0) ? 16u : 0u;
        adst[j] = (uint32_t)(row * A_STRIDE + pc * 4) * 4u;
        int kr = p >> 5, np = p & 31;
        gsrc[j] = gpe + (size_t)kr * HID + np * 4;
        usrc[j] = upe + (size_t)kr * HID + np * 4;
        bdst[j] = (uint32_t)(kr * B_STRIDE + np * 4) * 4u;
    }

    float cg[2][8][4] = {}, cu[2][8][4] = {};
    int mlane = (wid & 3) * 32 + (lane >> 2);
    int nb = (wid >> 2) * 64 + (lane >> 2);
    int kl = lane & 3;

    // prologue: chunk 0
    {
        uint32_t st0 = sbase;
#pragma unroll
        for (int j = 0; j < 2; j++) {
            CP16Z(st0 + adst[j], asrc[j], asz[j]);
            CP16(st0 + A_WORDS * 4 + bdst[j], gsrc[j]);
            CP16(st0 + (A_WORDS + B_WORDS) * 4 + bdst[j], usrc[j]);
        }
        CP_COMMIT();
    }

    const int NC = DM / BK;   // 64
    for (int c = 0; c < NC; ++c) {
        CP_WAIT0();
        __syncthreads();
        if (c + 1 < NC) {
            int k0 = (c + 1) * BK;
            size_t bko = (size_t)k0 * HID;
            uint32_t stn = sbase + (uint32_t)(((c + 1) & 1) * F1_STAGE * 4);
#pragma unroll
            for (int j = 0; j < 2; j++) {
                CP16Z(stn + adst[j], asrc[j] + k0, asz[j]);
                CP16(stn + A_WORDS * 4 + bdst[j], gsrc[j] + bko);
                CP16(stn + (A_WORDS + B_WORDS) * 4 + bdst[j], usrc[j] + bko);
            }
            CP_COMMIT();
        }
        // compute chunk c
        const uint32_t* A = sm + (c & 1) * F1_STAGE;
        const uint32_t* G = A + A_WORDS;
        const uint32_t* U = G + B_WORDS;
#pragma unroll
        for (int s = 0; s < 2; s++) {
            int ks = 8 * s + kl;
            uint32_t a[2][4];
#pragma unroll
            for (int mi = 0; mi < 2; mi++) {
                int m = mlane + mi * 16;
                a[mi][0] = A[m * A_STRIDE + ks];
                a[mi][1] = A[(m + 8) * A_STRIDE + ks];
                a[mi][2] = A[m * A_STRIDE + ks + 4];
                a[mi][3] = A[(m + 8) * A_STRIDE + ks + 4];
            }
#pragma unroll
            for (int ni = 0; ni < 8; ni++) {
                int n = nb + ni * 8;
                uint32_t g0 = G[ks * B_STRIDE + n], g1 = G[(ks + 4) * B_STRIDE + n];
                uint32_t u0 = U[ks * B_STRIDE + n], u1 = U[(ks + 4) * B_STRIDE + n];
                mma8(cg[0][ni], a[0], g0, g1);
                mma8(cg[1][ni], a[1], g0, g1);
                mma8(cu[0][ni], a[0], u0, u1);
                mma8(cu[1][ni], a[1], u0, u1);
            }
        }
    }

    // epilogue: h = (g + gpb) * silu(u + upb), pre-rounded to tf32 -> g_H
    const float* gpb = gp_b + e * HID + n0;
    const float* upb = up_b + e * HID + n0;
    int rrow = rb + (wid & 3) * 32 + (lane >> 2);
    int cbase = (wid >> 2) * 64 + 2 * (lane & 3);
#pragma unroll
    for (int ni = 0; ni < 8; ni++) {
        int col = cbase + ni * 8;
        float gb0 = gpb[col], gb1 = gpb[col + 1];
        float ub0 = upb[col], ub1 = upb[col + 1];
#pragma unroll
        for (int mi = 0; mi < 2; mi++) {
            int r0 = rrow + mi * 16;
            float g, u;
            float2 h;
            g = cg[mi][ni][0] + gb0; u = cu[mi][ni][0] + ub0;
            h.x = f2tf(g * (u / (1.f + expf(-u))));
            g = cg[mi][ni][1] + gb1; u = cu[mi][ni][1] + ub1;
            h.y = f2tf(g * (u / (1.f + expf(-u))));
            *(float2*)(g_H + (size_t)r0 * HID + n0 + col) = h;
            g = cg[mi][ni][2] + gb0; u = cu[mi][ni][2] + ub0;
            h.x = f2tf(g * (u / (1.f + expf(-u))));
            g = cg[mi][ni][3] + gb1; u = cu[mi][ni][3] + ub1;
            h.y = f2tf(g * (u / (1.f + expf(-u))));
            *(float2*)(g_H + (size_t)(r0 + 8) * HID + n0 + col) = h;
        }
    }
}

// ============ FFN stage 2: Y = H @ dp_w ============
__global__ void __launch_bounds__(256, 2)
ffn2_mma() {
    int mt = blockIdx.x;
    int e = g_tile_e[mt];
    if (e < 0) return;
    int rb = g_tile_base[mt];
    int n0 = blockIdx.y * BNT;

    __shared__ uint32_t sm2[2 * F2_STAGE];

    int tid = threadIdx.x, lane = tid & 31, wid = tid >> 5;
    uint32_t sbase = smem_u32(sm2);
    const float* dpe = g_dpr + (size_t)e * HID * DM + n0;

    const float* asrc[2]; uint32_t adst[2];
    const float* bsrc[2]; uint32_t bdst[2];
#pragma unroll
    for (int j = 0; j < 2; j++) {
        int p = tid + 256 * j;
        int row = p >> 2, pc = p & 3;
        asrc[j] = g_H + (size_t)(rb + row) * HID + pc * 4;
        adst[j] = (uint32_t)(row * A_STRIDE + pc * 4) * 4u;
        int kr = p >> 5, np = p & 31;
        bsrc[j] = dpe + (size_t)kr * DM + np * 4;
        bdst[j] = (uint32_t)(kr * B_STRIDE + np * 4) * 4u;
    }

    float ca[2][8][4] = {};
    int mlane = (wid & 3) * 32 + (lane >> 2);
    int nb = (wid >> 2) * 64 + (lane >> 2);
    int kl = lane & 3;

    {
#pragma unroll
        for (int j = 0; j < 2; j++) {
            CP16(sbase + adst[j], asrc[j]);
            CP16(sbase + A_WORDS * 4 + bdst[j], bsrc[j]);
        }
        CP_COMMIT();
    }

    const int NC = HID / BK;   // 32
    for (int c = 0; c < NC; ++c) {
        CP_WAIT0();
        __syncthreads();
        if (c + 1 < NC) {
            int k0 = (c + 1) * BK;
            size_t bko = (size_t)k0 * DM;
            uint32_t stn = sbase + (uint32_t)(((c + 1) & 1) * F2_STAGE * 4);
#pragma unroll
            for (int j = 0; j < 2; j++) {
                CP16(stn + adst[j], asrc[j] + k0);
                CP16(stn + A_WORDS * 4 + bdst[j], bsrc[j] + bko);
            }
            CP_COMMIT();
        }
        const uint32_t* A = sm2 + (c & 1) * F2_STAGE;
        const uint32_t* B = A + A_WORDS;
#pragma unroll
        for (int s = 0; s < 2; s++) {
            int ks = 8 * s + kl;
            uint32_t a[2][4];
#pragma unroll
            for (int mi = 0; mi < 2; mi++) {
                int m = mlane + mi * 16;
                a[mi][0] = A[m * A_STRIDE + ks];
                a[mi][1] = A[(m + 8) * A_STRIDE + ks];
                a[mi][2] = A[m * A_STRIDE + ks + 4];
                a[mi][3] = A[(m + 8) * A_STRIDE + ks + 4];
            }
#pragma unroll
            for (int ni = 0; ni < 8; ni++) {
                int n = nb + ni * 8;
                uint32_t b0 = B[ks * B_STRIDE + n], b1 = B[(ks + 4) * B_STRIDE + n];
                mma8(ca[0][ni], a[0], b0, b1);
                mma8(ca[1][ni], a[1], b0, b1);
            }
        }
    }

    int rrow = rb + (wid & 3) * 32 + (lane >> 2);
    int cbase = (wid >> 2) * 64 + 2 * (lane & 3);
#pragma unroll
    for (int ni = 0; ni < 8; ni++) {
        int col = n0 + cbase + ni * 8;
#pragma unroll
        for (int mi = 0; mi < 2; mi++) {
            int r0 = rrow + mi * 16;
            *(float2*)(g_Y + (size_t)r0 * DM + col) =
                make_float2(ca[mi][ni][0], ca[mi][ni][1]);
            *(float2*)(g_Y + (size_t)(r0 + 8) * DM + col) =
                make_float2(ca[mi][ni][2], ca[mi][ni][3]);
        }
    }
}

// combine: out[t] = w1*(Y[p1]+b_e1) + w2*(Y[p2]+b_e2)  (writes ALL of out[0..TD))
__global__ void __launch_bounds__(256)
combine_kernel(const float* __restrict__ dp_b, float* __restrict__ out) {
    int t = blockIdx.x;
    int c = threadIdx.x;
    int e1 = g_tok_idx[2 * t], e2 = g_tok_idx[2 * t + 1];
    float w1 = g_tok_w[2 * t], w2 = g_tok_w[2 * t + 1];
    int p1 = g_tok_pos[2 * t], p2 = g_tok_pos[2 * t + 1];
    float4 y1 = ((const float4*)(g_Y + (size_t)p1 * DM))[c];
    float4 y2 = ((const float4*)(g_Y + (size_t)p2 * DM))[c];
    float4 b1 = ((const float4*)(dp_b + (size_t)e1 * DM))[c];
    float4 b2 = ((const float4*)(dp_b + (size_t)e2 * DM))[c];
    float4 r;
    r.x = w1 * (y1.x + b1.x) + w2 * (y2.x + b2.x);
    r.y = w1 * (y1.y + b1.y) + w2 * (y2.y + b2.y);
    r.z = w1 * (y1.z + b1.z) + w2 * (y2.z + b2.z);
    r.w = w1 * (y1.w + b1.w) + w2 * (y2.w + b2.w);
    ((float4*)out)[(size_t)t * (DM / 4) + c] = r;
}

// ---------------- launcher ----------------
extern "C" void kernel_launch(void* const* d_in, const int* in_sizes, int n_in,
                              void* d_out, int out_size) {
    const float* x   = (const float*)d_in[0];
    const float* gw  = (const float*)d_in[1];
    const float* gb  = (const float*)d_in[2];
    const float* gpw = (const float*)d_in[3];
    const float* gpb = (const float*)d_in[4];
    const float* upw = (const float*)d_in[5];
    const float* upb = (const float*)d_in[6];
    const float* dpw = (const float*)d_in[7];
    const float* dpb = (const float*)d_in[8];
    float* out = (float*)d_out;

    static int attr_done = 0;
    if (!attr_done) {
        cudaFuncSetAttribute(ffn1_mma, cudaFuncAttributeMaxDynamicSharedMemorySize,
                             F1_SMEM);
        attr_done = 1;
    }

    init_kernel<<<1, 32>>>();
    gate_kernel<<<(T_TOK * 32 + 255) / 256, 256>>>(x, gw, gb);
    scan_kernel<<<1, 1>>>();
    scatter_kernel<<<(T_TOK + 255) / 256, 256>>>();
    round_all<<<2048, 256>>>(x, gpw, upw, dpw);
    aux_kernel<<<1, 32>>>(out, (long)out_size);

    ffn1_mma<<<dim3(MTILES, HID / BNT), 256, F1_SMEM>>>(gpb, upb);
    ffn2_mma<<<dim3(MTILES, DM / BNT), 256>>>();
    combine_kernel<<<T_TOK, 256>>>(dpb, out);
}

// round 10
// speedup vs baseline: 2.3346x; 1.0151x over previous
#include <cuda_runtime.h>
#include <math.h>
#include <stdint.h>

// ---------------- problem constants ----------------
#define T_TOK 16384
#define DM    1024
#define HID   512
#define NE    16
#define TOPK  2

// ---------------- tiling ----------------
#define BMT 128
#define BNT 128
#define BK  16
#define MTILES 272
#define PAD_ROWS (MTILES * BMT)

#define A_STRIDE 20
#define B_STRIDE 136
#define A_WORDS (128 * A_STRIDE)           // 2560
#define B_WORDS (BK * B_STRIDE)            // 2176
#define F1_STAGE (A_WORDS + 2 * B_WORDS)   // 6912 words
#define F2_STAGE (A_WORDS + B_WORDS)       // 4736 words
#define S1 4
#define S2 3
#define F1_SMEM (S1 * F1_STAGE * 4)        // 110592 bytes
#define F2_SMEM (S2 * F2_STAGE * 4)        // 56832 bytes

// ---------------- static scratch ----------------
__device__ int   g_counts[NE];
__device__ int   g_cursor[NE];
__device__ int   g_off[NE];
__device__ int   g_tile_e[MTILES];
__device__ int   g_tile_base[MTILES];
__device__ int   g_tok_idx[T_TOK * TOPK];
__device__ float g_tok_w[T_TOK * TOPK];
__device__ int   g_tok_pos[T_TOK * TOPK];
__device__ int   g_row_tok[PAD_ROWS];
__device__ __align__(16) float g_Xr[(size_t)T_TOK * DM];
__device__ __align__(16) float g_gpr[(size_t)NE * DM * HID];
__device__ __align__(16) float g_upr[(size_t)NE * DM * HID];
__device__ __align__(16) float g_dpr[(size_t)NE * HID * DM];
__device__ __align__(16) float g_H[(size_t)PAD_ROWS * HID];
__device__ __align__(16) float g_Y[(size_t)PAD_ROWS * DM];

// ---------------- helpers ----------------
__device__ __forceinline__ uint32_t smem_u32(const void* p) {
    uint32_t a;
    asm("{ .reg .u64 t; cvta.to.shared.u64 t, %1; cvt.u32.u64 %0, t; }" : "=r"(a) : "l"(p));
    return a;
}

__device__ __forceinline__ float f2tf(float f) {
    uint32_t r;
    asm("cvt.rna.tf32.f32 %0, %1;" : "=r"(r) : "f"(f));
    return __uint_as_float(r);
}

__device__ __forceinline__ void mma8(float c[4], const uint32_t a[4],
                                     uint32_t b0, uint32_t b1) {
    asm volatile(
        "mma.sync.aligned.m16n8k8.row.col.f32.tf32.tf32.f32 "
        "{%0,%1,%2,%3}, {%4,%5,%6,%7}, {%8,%9}, {%0,%1,%2,%3};"
        : "+f"(c[0]), "+f"(c[1]), "+f"(c[2]), "+f"(c[3])
        : "r"(a[0]), "r"(a[1]), "r"(a[2]), "r"(a[3]), "r"(b0), "r"(b1));
}

#define CP16(dst, src) \
    asm volatile("cp.async.cg.shared.global [%0], [%1], 16;" :: "r"(dst), "l"(src))
#define CP16Z(dst, src, sz) \
    asm volatile("cp.async.cg.shared.global [%0], [%1], 16, %2;" :: "r"(dst), "l"(src), "r"(sz))
#define CP_COMMIT() asm volatile("cp.async.commit_group;" ::: "memory")
#define CP_WAIT(n)  asm volatile("cp.async.wait_group %0;" :: "n"(n) : "memory")

// ---------------- routing kernels ----------------
__global__ void init_kernel() {
    int i = threadIdx.x;
    if (i < NE) g_counts[i] = 0;
}

// gate + fused tf32 rounding of x into g_Xr
__global__ void gate_kernel(const float* __restrict__ x,
                            const float* __restrict__ gw,
                            const float* __restrict__ gb) {
    int gid = blockIdx.x * blockDim.x + threadIdx.x;
    int t = gid >> 5, lane = gid & 31;
    if (t >= T_TOK) return;
    const float* xr = x + (size_t)t * DM;
    float* xo = g_Xr + (size_t)t * DM;
    float acc[NE];
#pragma unroll
    for (int e = 0; e < NE; e++) acc[e] = 0.f;
    for (int d = lane; d < DM; d += 32) {
        float xv = xr[d];
        xo[d] = f2tf(xv);
        const float* g = gw + d * NE;
#pragma unroll
        for (int e = 0; e < NE; e++) acc[e] = fmaf(xv, g[e], acc[e]);
    }
#pragma unroll
    for (int e = 0; e < NE; e++)
#pragma unroll
        for (int o = 16; o > 0; o >>= 1)
            acc[e] += __shfl_xor_sync(0xffffffffu, acc[e], o);
    if (lane == 0) {
        float s[NE], mx = -1e30f;
#pragma unroll
        for (int e = 0; e < NE; e++) { s[e] = acc[e] + gb[e]; mx = fmaxf(mx, s[e]); }
        float sum = 0.f;
#pragma unroll
        for (int e = 0; e < NE; e++) { s[e] = expf(s[e] - mx); sum += s[e]; }
        int i1 = 0; float v1 = -1.f;
#pragma unroll
        for (int e = 0; e < NE; e++) if (s[e] > v1) { v1 = s[e]; i1 = e; }
        int i2 = 0; float v2 = -1.f;
#pragma unroll
        for (int e = 0; e < NE; e++) if (e != i1 && s[e] > v2) { v2 = s[e]; i2 = e; }
        float p1 = v1 / sum, p2 = v2 / sum;
        float den = p1 + p2 + 1e-9f;
        g_tok_idx[2 * t + 0] = i1; g_tok_w[2 * t + 0] = p1 / den;
        g_tok_idx[2 * t + 1] = i2; g_tok_w[2 * t + 1] = p2 / den;
        atomicAdd(&g_counts[i1], 1);
        atomicAdd(&g_counts[i2], 1);
    }
}

__global__ void scan_kernel() {
    int off = 0, tile = 0;
    for (int e = 0; e < NE; e++) {
        g_off[e] = off; g_cursor[e] = 0;
        int c = g_counts[e];
        int nt = (c + BMT - 1) / BMT;
        for (int j = 0; j < nt; j++) {
            g_tile_e[tile] = e;
            g_tile_base[tile] = off + j * BMT;
            tile++;
        }
        for (int r = off + c; r < off + nt * BMT; r++) g_row_tok[r] = -1;
        off += nt * BMT;
    }
    for (; tile < MTILES; tile++) g_tile_e[tile] = -1;
}

__global__ void scatter_kernel() {
    int t = blockIdx.x * blockDim.x + threadIdx.x;
    if (t >= T_TOK) return;
#pragma unroll
    for (int k = 0; k < TOPK; k++) {
        int e = g_tok_idx[2 * t + k];
        int pos = g_off[e] + atomicAdd(&g_cursor[e], 1);
        g_row_tok[pos] = t;
        g_tok_pos[2 * t + k] = pos;
    }
}

__global__ void aux_kernel(float* out, long out_size) {
    if (blockIdx.x == 0 && threadIdx.x == 0) {
        const float cap = 1.25f * (float)(T_TOK * TOPK) / (float)NE;
        float sum = 0.f;
        for (int e = 0; e < NE; e++) {
            float l = (float)g_counts[e] - cap;
            if (l > 0.f) sum += l;
        }
        float aux = 0.01f * sum / (float)NE / (float)T_TOK;
        long TD = (long)T_TOK * DM;
        if (out_size > TD) out[TD] = aux;
    }
}

// round gp / up / dp to tf32
__global__ void round_weights(const float* __restrict__ gp,
                              const float* __restrict__ up,
                              const float* __restrict__ dp) {
    const long NW = (long)NE * DM * HID / 4;
    long i = blockIdx.x * (long)blockDim.x + threadIdx.x;
    long st = (long)gridDim.x * blockDim.x;
    for (; i < 3 * NW; i += st) {
        const float4* s; float4* d; long j;
        if (i < NW)          { s = (const float4*)gp; d = (float4*)g_gpr; j = i; }
        else if (i < 2 * NW) { s = (const float4*)up; d = (float4*)g_upr; j = i - NW; }
        else                 { s = (const float4*)dp; d = (float4*)g_dpr; j = i - 2 * NW; }
        float4 v = s[j];
        v.x = f2tf(v.x); v.y = f2tf(v.y); v.z = f2tf(v.z); v.w = f2tf(v.w);
        d[j] = v;
    }
}

// ============ FFN stage 1: H = (X@gp + b) * silu(X@up + b) ============
__global__ void __launch_bounds__(256)
ffn1_mma(const float* __restrict__ gp_b, const float* __restrict__ up_b) {
    int mt = blockIdx.x;
    int e = g_tile_e[mt];
    if (e < 0) return;
    int rb = g_tile_base[mt];
    int n0 = blockIdx.y * BNT;

    extern __shared__ uint32_t sm[];
    __shared__ int s_toks[BMT];

    int tid = threadIdx.x, lane = tid & 31, wid = tid >> 5;
    if (tid < BMT) s_toks[tid] = g_row_tok[rb + tid];
    __syncthreads();

    uint32_t sbase = smem_u32(sm);
    const float* gpe = g_gpr + (size_t)e * DM * HID + n0;
    const float* upe = g_upr + (size_t)e * DM * HID + n0;

    const float* asrc[2]; uint32_t asz[2], adst[2];
    const float* gsrc[2]; const float* usrc[2]; uint32_t bdst[2];
#pragma unroll
    for (int j = 0; j < 2; j++) {
        int p = tid + 256 * j;
        int row = p >> 2, pc = p & 3;
        int tok = s_toks[row];
        asrc[j] = g_Xr + (size_t)(tok >= 0 ? tok : 0) * DM + pc * 4;
        asz[j]  = (tok >= 0) ? 16u : 0u;
        adst[j] = (uint32_t)(row * A_STRIDE + pc * 4) * 4u;
        int kr = p >> 5, np = p & 31;
        gsrc[j] = gpe + (size_t)kr * HID + np * 4;
        usrc[j] = upe + (size_t)kr * HID + np * 4;
        bdst[j] = (uint32_t)(kr * B_STRIDE + np * 4) * 4u;
    }

    float cg[2][8][4] = {}, cu[2][8][4] = {};
    int mlane = (wid & 3) * 32 + (lane >> 2);
    int nb = (wid >> 2) * 64 + (lane >> 2);
    int kl = lane & 3;

    const int NC = DM / BK;   // 64
    // prologue: chunks 0..S1-2
#pragma unroll
    for (int pc = 0; pc < S1 - 1; pc++) {
        uint32_t stg = sbase + (uint32_t)(pc * F1_STAGE * 4);
        int k0 = pc * BK;
        size_t bko = (size_t)k0 * HID;
#pragma unroll
        for (int j = 0; j < 2; j++) {
            CP16Z(stg + adst[j], asrc[j] + k0, asz[j]);
            CP16(stg + A_WORDS * 4 + bdst[j], gsrc[j] + bko);
            CP16(stg + (A_WORDS + B_WORDS) * 4 + bdst[j], usrc[j] + bko);
        }
        CP_COMMIT();
    }

    for (int c = 0; c < NC; ++c) {
        CP_WAIT(S1 - 2);
        __syncthreads();
        int cn = c + S1 - 1;
        if (cn < NC) {
            int k0 = cn * BK;
            size_t bko = (size_t)k0 * HID;
            uint32_t stg = sbase + (uint32_t)((cn & (S1 - 1)) * F1_STAGE * 4);
#pragma unroll
            for (int j = 0; j < 2; j++) {
                CP16Z(stg + adst[j], asrc[j] + k0, asz[j]);
                CP16(stg + A_WORDS * 4 + bdst[j], gsrc[j] + bko);
                CP16(stg + (A_WORDS + B_WORDS) * 4 + bdst[j], usrc[j] + bko);
            }
        }
        CP_COMMIT();
        const uint32_t* A = sm + (c & (S1 - 1)) * F1_STAGE;
        const uint32_t* G = A + A_WORDS;
        const uint32_t* U = G + B_WORDS;
#pragma unroll
        for (int s = 0; s < 2; s++) {
            int ks = 8 * s + kl;
            uint32_t a[2][4];
#pragma unroll
            for (int mi = 0; mi < 2; mi++) {
                int m = mlane + mi * 16;
                a[mi][0] = A[m * A_STRIDE + ks];
                a[mi][1] = A[(m + 8) * A_STRIDE + ks];
                a[mi][2] = A[m * A_STRIDE + ks + 4];
                a[mi][3] = A[(m + 8) * A_STRIDE + ks + 4];
            }
#pragma unroll
            for (int ni = 0; ni < 8; ni++) {
                int n = nb + ni * 8;
                uint32_t g0 = G[ks * B_STRIDE + n], g1 = G[(ks + 4) * B_STRIDE + n];
                uint32_t u0 = U[ks * B_STRIDE + n], u1 = U[(ks + 4) * B_STRIDE + n];
                mma8(cg[0][ni], a[0], g0, g1);
                mma8(cg[1][ni], a[1], g0, g1);
                mma8(cu[0][ni], a[0], u0, u1);
                mma8(cu[1][ni], a[1], u0, u1);
            }
        }
    }

    const float* gpb = gp_b + e * HID + n0;
    const float* upb = up_b + e * HID + n0;
    int rrow = rb + (wid & 3) * 32 + (lane >> 2);
    int cbase = (wid >> 2) * 64 + 2 * (lane & 3);
#pragma unroll
    for (int ni = 0; ni < 8; ni++) {
        int col = cbase + ni * 8;
        float gb0 = gpb[col], gb1 = gpb[col + 1];
        float ub0 = upb[col], ub1 = upb[col + 1];
#pragma unroll
        for (int mi = 0; mi < 2; mi++) {
            int r0 = rrow + mi * 16;
            float g, u;
            float2 h;
            g = cg[mi][ni][0] + gb0; u = cu[mi][ni][0] + ub0;
            h.x = f2tf(g * (u / (1.f + expf(-u))));
            g = cg[mi][ni][1] + gb1; u = cu[mi][ni][1] + ub1;
            h.y = f2tf(g * (u / (1.f + expf(-u))));
            *(float2*)(g_H + (size_t)r0 * HID + n0 + col) = h;
            g = cg[mi][ni][2] + gb0; u = cu[mi][ni][2] + ub0;
            h.x = f2tf(g * (u / (1.f + expf(-u))));
            g = cg[mi][ni][3] + gb1; u = cu[mi][ni][3] + ub1;
            h.y = f2tf(g * (u / (1.f + expf(-u))));
            *(float2*)(g_H + (size_t)(r0 + 8) * HID + n0 + col) = h;
        }
    }
}

// ============ FFN stage 2: Y = H @ dp_w ============
__global__ void __launch_bounds__(256, 2)
ffn2_mma() {
    int mt = blockIdx.x;
    int e = g_tile_e[mt];
    if (e < 0) return;
    int rb = g_tile_base[mt];
    int n0 = blockIdx.y * BNT;

    extern __shared__ uint32_t sm2[];

    int tid = threadIdx.x, lane = tid & 31, wid = tid >> 5;
    uint32_t sbase = smem_u32(sm2);
    const float* dpe = g_dpr + (size_t)e * HID * DM + n0;

    const float* asrc[2]; uint32_t adst[2];
    const float* bsrc[2]; uint32_t bdst[2];
#pragma unroll
    for (int j = 0; j < 2; j++) {
        int p = tid + 256 * j;
        int row = p >> 2, pc = p & 3;
        asrc[j] = g_H + (size_t)(rb + row) * HID + pc * 4;
        adst[j] = (uint32_t)(row * A_STRIDE + pc * 4) * 4u;
        int kr = p >> 5, np = p & 31;
        bsrc[j] = dpe + (size_t)kr * DM + np * 4;
        bdst[j] = (uint32_t)(kr * B_STRIDE + np * 4) * 4u;
    }

    float ca[2][8][4] = {};
    int mlane = (wid & 3) * 32 + (lane >> 2);
    int nb = (wid >> 2) * 64 + (lane >> 2);
    int kl = lane & 3;

    const int NC = HID / BK;   // 32
#pragma unroll
    for (int pc = 0; pc < S2 - 1; pc++) {
        uint32_t stg = sbase + (uint32_t)(pc * F2_STAGE * 4);
        int k0 = pc * BK;
        size_t bko = (size_t)k0 * DM;
#pragma unroll
        for (int j = 0; j < 2; j++) {
            CP16(stg + adst[j], asrc[j] + k0);
            CP16(stg + A_WORDS * 4 + bdst[j], bsrc[j] + bko);
        }
        CP_COMMIT();
    }

    for (int c = 0; c < NC; ++c) {
        CP_WAIT(S2 - 2);
        __syncthreads();
        int cn = c + S2 - 1;
        if (cn < NC) {
            int k0 = cn * BK;
            size_t bko = (size_t)k0 * DM;
            uint32_t stg = sbase + (uint32_t)((cn % S2) * F2_STAGE * 4);
#pragma unroll
            for (int j = 0; j < 2; j++) {
                CP16(stg + adst[j], asrc[j] + k0);
                CP16(stg + A_WORDS * 4 + bdst[j], bsrc[j] + bko);
            }
        }
        CP_COMMIT();
        const uint32_t* A = sm2 + (c % S2) * F2_STAGE;
        const uint32_t* B = A + A_WORDS;
#pragma unroll
        for (int s = 0; s < 2; s++) {
            int ks = 8 * s + kl;
            uint32_t a[2][4];
#pragma unroll
            for (int mi = 0; mi < 2; mi++) {
                int m = mlane + mi * 16;
                a[mi][0] = A[m * A_STRIDE + ks];
                a[mi][1] = A[(m + 8) * A_STRIDE + ks];
                a[mi][2] = A[m * A_STRIDE + ks + 4];
                a[mi][3] = A[(m + 8) * A_STRIDE + ks + 4];
            }
#pragma unroll
            for (int ni = 0; ni < 8; ni++) {
                int n = nb + ni * 8;
                uint32_t b0 = B[ks * B_STRIDE + n], b1 = B[(ks + 4) * B_STRIDE + n];
                mma8(ca[0][ni], a[0], b0, b1);
                mma8(ca[1][ni], a[1], b0, b1);
            }
        }
    }

    int rrow = rb + (wid & 3) * 32 + (lane >> 2);
    int cbase = (wid >> 2) * 64 + 2 * (lane & 3);
#pragma unroll
    for (int ni = 0; ni < 8; ni++) {
        int col = n0 + cbase + ni * 8;
#pragma unroll
        for (int mi = 0; mi < 2; mi++) {
            int r0 = rrow + mi * 16;
            *(float2*)(g_Y + (size_t)r0 * DM + col) =
                make_float2(ca[mi][ni][0], ca[mi][ni][1]);
            *(float2*)(g_Y + (size_t)(r0 + 8) * DM + col) =
                make_float2(ca[mi][ni][2], ca[mi][ni][3]);
        }
    }
}

// combine: out[t] = w1*(Y[p1]+b_e1) + w2*(Y[p2]+b_e2)
__global__ void __launch_bounds__(256)
combine_kernel(const float* __restrict__ dp_b, float* __restrict__ out) {
    int t = blockIdx.x;
    int c = threadIdx.x;
    int e1 = g_tok_idx[2 * t], e2 = g_tok_idx[2 * t + 1];
    float w1 = g_tok_w[2 * t], w2 = g_tok_w[2 * t + 1];
    int p1 = g_tok_pos[2 * t], p2 = g_tok_pos[2 * t + 1];
    float4 y1 = ((const float4*)(g_Y + (size_t)p1 * DM))[c];
    float4 y2 = ((const float4*)(g_Y + (size_t)p2 * DM))[c];
    float4 b1 = ((const float4*)(dp_b + (size_t)e1 * DM))[c];
    float4 b2 = ((const float4*)(dp_b + (size_t)e2 * DM))[c];
    float4 r;
    r.x = w1 * (y1.x + b1.x) + w2 * (y2.x + b2.x);
    r.y = w1 * (y1.y + b1.y) + w2 * (y2.y + b2.y);
    r.z = w1 * (y1.z + b1.z) + w2 * (y2.z + b2.z);
    r.w = w1 * (y1.w + b1.w) + w2 * (y2.w + b2.w);
    ((float4*)out)[(size_t)t * (DM / 4) + c] = r;
}

// ---------------- launcher ----------------
extern "C" void kernel_launch(void* const* d_in, const int* in_sizes, int n_in,
                              void* d_out, int out_size) {
    const float* x   = (const float*)d_in[0];
    const float* gw  = (const float*)d_in[1];
    const float* gb  = (const float*)d_in[2];
    const float* gpw = (const float*)d_in[3];
    const float* gpb = (const float*)d_in[4];
    const float* upw = (const float*)d_in[5];
    const float* upb = (const float*)d_in[6];
    const float* dpw = (const float*)d_in[7];
    const float* dpb = (const float*)d_in[8];
    float* out = (float*)d_out;

    static int attr_done = 0;
    if (!attr_done) {
        cudaFuncSetAttribute(ffn1_mma, cudaFuncAttributeMaxDynamicSharedMemorySize,
                             F1_SMEM);
        cudaFuncSetAttribute(ffn2_mma, cudaFuncAttributeMaxDynamicSharedMemorySize,
                             F2_SMEM);
        attr_done = 1;
    }

    init_kernel<<<1, 32>>>();
    gate_kernel<<<(T_TOK * 32 + 255) / 256, 256>>>(x, gw, gb);
    scan_kernel<<<1, 1>>>();
    scatter_kernel<<<(T_TOK + 255) / 256, 256>>>();
    round_weights<<<2048, 256>>>(gpw, upw, dpw);
    aux_kernel<<<1, 32>>>(out, (long)out_size);

    ffn1_mma<<<dim3(MTILES, HID / BNT), 256, F1_SMEM>>>(gpb, upb);
    ffn2_mma<<<dim3(MTILES, DM / BNT), 256, F2_SMEM>>>();
    combine_kernel<<<T_TOK, 256>>>(dpb, out);
}

// round 12
// speedup vs baseline: 3.0285x; 1.2973x over previous
#include <cuda_runtime.h>
#include <cuda_fp16.h>
#include <math.h>
#include <stdint.h>

// ---------------- problem constants ----------------
#define T_TOK 16384
#define DM    1024
#define HID   512
#define NE    16
#define TOPK  2

// ---------------- tiling ----------------
#define BMT 128
#define BNT 128
#define BK  32                         // k-halves per pipeline chunk
#define MTILES 272
#define PAD_ROWS (MTILES * BMT)

#define TSTRIDE 20                     // words per tile row (16 data + 4 pad)
#define TILE_WORDS (128 * TSTRIDE)     // 2560 words per 128x32-half tile
#define F1_STAGE (3 * TILE_WORDS)      // A + G + U = 7680 words
#define F2_STAGE (2 * TILE_WORDS)      // A + B = 5120 words
#define S1 4
#define S2 3
#define F1_SMEM (S1 * F1_STAGE * 4)    // 122880 B
#define F2_SMEM (S2 * F2_STAGE * 4)    // 61440 B

// ---------------- static scratch ----------------
__device__ int   g_counts[NE];
__device__ int   g_cursor[NE];
__device__ int   g_off[NE];
__device__ int   g_tile_e[MTILES];
__device__ int   g_tile_base[MTILES];
__device__ int   g_tok_idx[T_TOK * TOPK];
__device__ float g_tok_w[T_TOK * TOPK];
__device__ int   g_tok_pos[T_TOK * TOPK];
__device__ int   g_row_tok[PAD_ROWS];
__device__ __align__(16) __half g_Xh[(size_t)T_TOK * DM];
__device__ __align__(16) __half g_gph[(size_t)NE * HID * DM];   // [e][n][k]
__device__ __align__(16) __half g_uph[(size_t)NE * HID * DM];   // [e][n][k]
__device__ __align__(16) __half g_dph[(size_t)NE * DM * HID];   // [e][n][k]
__device__ __align__(16) __half g_H[(size_t)PAD_ROWS * HID];
__device__ __align__(16) float  g_Y[(size_t)PAD_ROWS * DM];

// ---------------- helpers ----------------
__device__ __forceinline__ uint32_t smem_u32(const void* p) {
    uint32_t a;
    asm("{ .reg .u64 t; cvta.to.shared.u64 t, %1; cvt.u32.u64 %0, t; }" : "=r"(a) : "l"(p));
    return a;
}

__device__ __forceinline__ void mma16(float c[4], const uint32_t a[4],
                                      uint32_t b0, uint32_t b1) {
    asm volatile(
        "mma.sync.aligned.m16n8k16.row.col.f32.f16.f16.f32 "
        "{%0,%1,%2,%3}, {%4,%5,%6,%7}, {%8,%9}, {%0,%1,%2,%3};"
        : "+f"(c[0]), "+f"(c[1]), "+f"(c[2]), "+f"(c[3])
        : "r"(a[0]), "r"(a[1]), "r"(a[2]), "r"(a[3]), "r"(b0), "r"(b1));
}

#define CP16(dst, src) \
    asm volatile("cp.async.cg.shared.global [%0], [%1], 16;" :: "r"(dst), "l"(src))
#define CP16Z(dst, src, sz) \
    asm volatile("cp.async.cg.shared.global [%0], [%1], 16, %2;" :: "r"(dst), "l"(src), "r"(sz))
#define CP_COMMIT() asm volatile("cp.async.commit_group;" ::: "memory")
#define CP_WAIT(n)  asm volatile("cp.async.wait_group %0;" :: "n"(n) : "memory")

// ---------------- routing kernels ----------------
__global__ void init_kernel() {
    int i = threadIdx.x;
    if (i < NE) g_counts[i] = 0;
}

// gate + fused fp16 conversion of x into g_Xh
__global__ void gate_kernel(const float* __restrict__ x,
                            const float* __restrict__ gw,
                            const float* __restrict__ gb) {
    int gid = blockIdx.x * blockDim.x + threadIdx.x;
    int t = gid >> 5, lane = gid & 31;
    if (t >= T_TOK) return;
    const float* xr = x + (size_t)t * DM;
    __half* xo = g_Xh + (size_t)t * DM;
    float acc[NE];
#pragma unroll
    for (int e = 0; e < NE; e++) acc[e] = 0.f;
    for (int d = lane; d < DM; d += 32) {
        float xv = xr[d];
        xo[d] = __float2half_rn(xv);
        const float* g = gw + d * NE;
#pragma unroll
        for (int e = 0; e < NE; e++) acc[e] = fmaf(xv, g[e], acc[e]);
    }
#pragma unroll
    for (int e = 0; e < NE; e++)
#pragma unroll
        for (int o = 16; o > 0; o >>= 1)
            acc[e] += __shfl_xor_sync(0xffffffffu, acc[e], o);
    if (lane == 0) {
        float s[NE], mx = -1e30f;
#pragma unroll
        for (int e = 0; e < NE; e++) { s[e] = acc[e] + gb[e]; mx = fmaxf(mx, s[e]); }
        float sum = 0.f;
#pragma unroll
        for (int e = 0; e < NE; e++) { s[e] = expf(s[e] - mx); sum += s[e]; }
        int i1 = 0; float v1 = -1.f;
#pragma unroll
        for (int e = 0; e < NE; e++) if (s[e] > v1) { v1 = s[e]; i1 = e; }
        int i2 = 0; float v2 = -1.f;
#pragma unroll
        for (int e = 0; e < NE; e++) if (e != i1 && s[e] > v2) { v2 = s[e]; i2 = e; }
        float p1 = v1 / sum, p2 = v2 / sum;
        float den = p1 + p2 + 1e-9f;
        g_tok_idx[2 * t + 0] = i1; g_tok_w[2 * t + 0] = p1 / den;
        g_tok_idx[2 * t + 1] = i2; g_tok_w[2 * t + 1] = p2 / den;
        atomicAdd(&g_counts[i1], 1);
        atomicAdd(&g_counts[i2], 1);
    }
}

__global__ void scan_kernel() {
    int off = 0, tile = 0;
    for (int e = 0; e < NE; e++) {
        g_off[e] = off; g_cursor[e] = 0;
        int c = g_counts[e];
        int nt = (c + BMT - 1) / BMT;
        for (int j = 0; j < nt; j++) {
            g_tile_e[tile] = e;
            g_tile_base[tile] = off + j * BMT;
            tile++;
        }
        for (int r = off + c; r < off + nt * BMT; r++) g_row_tok[r] = -1;
        off += nt * BMT;
    }
    for (; tile < MTILES; tile++) g_tile_e[tile] = -1;
}

__global__ void scatter_kernel() {
    int t = blockIdx.x * blockDim.x + threadIdx.x;
    if (t >= T_TOK) return;
#pragma unroll
    for (int k = 0; k < TOPK; k++) {
        int e = g_tok_idx[2 * t + k];
        int pos = g_off[e] + atomicAdd(&g_cursor[e], 1);
        g_row_tok[pos] = t;
        g_tok_pos[2 * t + k] = pos;
    }
}

__global__ void aux_kernel(float* out, long out_size) {
    if (blockIdx.x == 0 && threadIdx.x == 0) {
        const float cap = 1.25f * (float)(T_TOK * TOPK) / (float)NE;
        float sum = 0.f;
        for (int e = 0; e < NE; e++) {
            float l = (float)g_counts[e] - cap;
            if (l > 0.f) sum += l;
        }
        float aux = 0.01f * sum / (float)NE / (float)T_TOK;
        long TD = (long)T_TOK * DM;
        if (out_size > TD) out[TD] = aux;
    }
}

// weights [e][K][N] float -> [e][N][K] half
__global__ void transpose_w(const float* __restrict__ src, __half* __restrict__ dst,
                            int K, int N) {
    __shared__ float tile[32][33];
    int e = blockIdx.z;
    int k0 = blockIdx.y * 32, n0 = blockIdx.x * 32;
    src += (size_t)e * K * N;
    dst += (size_t)e * K * N;
    int tx = threadIdx.x, ty = threadIdx.y;
#pragma unroll
    for (int i = 0; i < 32; i += 8)
        tile[ty + i][tx] = src[(size_t)(k0 + ty + i) * N + n0 + tx];
    __syncthreads();
#pragma unroll
    for (int i = 0; i < 32; i += 8)
        dst[(size_t)(n0 + ty + i) * K + k0 + tx] = __float2half_rn(tile[tx][ty + i]);
}

// ============ FFN stage 1: H = (X@gp + b) * silu(X@up + b), fp16 mma ============
__global__ void __launch_bounds__(256)
ffn1_mma(const float* __restrict__ gp_b, const float* __restrict__ up_b) {
    int mt = blockIdx.x;
    int e = g_tile_e[mt];
    if (e < 0) return;
    int rb = g_tile_base[mt];
    int n0 = blockIdx.y * BNT;

    extern __shared__ uint32_t sm[];
    __shared__ int s_toks[BMT];

    int tid = threadIdx.x, lane = tid & 31, wid = tid >> 5;
    if (tid < BMT) s_toks[tid] = g_row_tok[rb + tid];
    __syncthreads();

    uint32_t sbase = smem_u32(sm);
    const __half* gpe = g_gph + (size_t)e * HID * DM;   // [n][k]
    const __half* upe = g_uph + (size_t)e * HID * DM;

    // loader mapping: row = p>>2 (0..127), pc = p&3 (16B piece within 32-half row)
    const __half* asrc[2]; uint32_t asz[2], tdst[2];
    const __half* gsrc[2]; const __half* usrc[2];
#pragma unroll
    for (int j = 0; j < 2; j++) {
        int p = tid + 256 * j;
        int row = p >> 2, pc = p & 3;
        int tok = s_toks[row];
        asrc[j] = g_Xh + (size_t)(tok >= 0 ? tok : 0) * DM + pc * 8;
        asz[j]  = (tok >= 0) ? 16u : 0u;
        gsrc[j] = gpe + (size_t)(n0 + row) * DM + pc * 8;
        usrc[j] = upe + (size_t)(n0 + row) * DM + pc * 8;
        tdst[j] = (uint32_t)(row * TSTRIDE + pc * 4) * 4u;
    }

    float cg[2][8][4] = {}, cu[2][8][4] = {};
    int mlane = (wid & 3) * 32 + (lane >> 2);
    int nbase = (wid >> 2) * 64 + (lane >> 2);
    int tig = lane & 3;

    const int NC = DM / BK;   // 32
#pragma unroll
    for (int pc = 0; pc < S1 - 1; pc++) {
        uint32_t stg = sbase + (uint32_t)(pc * F1_STAGE * 4);
        int k0 = pc * BK;
#pragma unroll
        for (int j = 0; j < 2; j++) {
            CP16Z(stg + tdst[j], asrc[j] + k0, asz[j]);
            CP16(stg + TILE_WORDS * 4 + tdst[j], gsrc[j] + k0);
            CP16(stg + 2 * TILE_WORDS * 4 + tdst[j], usrc[j] + k0);
        }
        CP_COMMIT();
    }

    for (int c = 0; c < NC; ++c) {
        CP_WAIT(S1 - 2);
        __syncthreads();
        int cn = c + S1 - 1;
        if (cn < NC) {
            int k0 = cn * BK;
            uint32_t stg = sbase + (uint32_t)((cn & (S1 - 1)) * F1_STAGE * 4);
#pragma unroll
            for (int j = 0; j < 2; j++) {
                CP16Z(stg + tdst[j], asrc[j] + k0, asz[j]);
                CP16(stg + TILE_WORDS * 4 + tdst[j], gsrc[j] + k0);
                CP16(stg + 2 * TILE_WORDS * 4 + tdst[j], usrc[j] + k0);
            }
        }
        CP_COMMIT();
        const uint32_t* A = sm + (c & (S1 - 1)) * F1_STAGE;
        const uint32_t* G = A + TILE_WORDS;
        const uint32_t* U = G + TILE_WORDS;
#pragma unroll
        for (int s = 0; s < 2; s++) {          // two k16 slices per chunk
            int ks = 8 * s + tig;
            uint32_t a[2][4];
#pragma unroll
            for (int mi = 0; mi < 2; mi++) {
                int m = mlane + mi * 16;
                a[mi][0] = A[m * TSTRIDE + ks];
                a[mi][1] = A[(m + 8) * TSTRIDE + ks];
                a[mi][2] = A[m * TSTRIDE + ks + 4];
                a[mi][3] = A[(m + 8) * TSTRIDE + ks + 4];
            }
#pragma unroll
            for (int ni = 0; ni < 8; ni++) {
                int n = nbase + ni * 8;
                uint32_t g0 = G[n * TSTRIDE + ks], g1 = G[n * TSTRIDE + ks + 4];
                uint32_t u0 = U[n * TSTRIDE + ks], u1 = U[n * TSTRIDE + ks + 4];
                mma16(cg[0][ni], a[0], g0, g1);
                mma16(cg[1][ni], a[1], g0, g1);
                mma16(cu[0][ni], a[0], u0, u1);
                mma16(cu[1][ni], a[1], u0, u1);
            }
        }
    }

    // epilogue: h = (g + gpb) * silu(u + upb) -> g_H (fp16)
    const float* gpb = gp_b + e * HID + n0;
    const float* upb = up_b + e * HID + n0;
    int rrow = rb + (wid & 3) * 32 + (lane >> 2);
    int cbase = (wid >> 2) * 64 + 2 * (lane & 3);
#pragma unroll
    for (int ni = 0; ni < 8; ni++) {
        int col = cbase + ni * 8;
        float gb0 = gpb[col], gb1 = gpb[col + 1];
        float ub0 = upb[col], ub1 = upb[col + 1];
#pragma unroll
        for (int mi = 0; mi < 2; mi++) {
            int r0 = rrow + mi * 16;
            float g, u, h0, h1;
            g = cg[mi][ni][0] + gb0; u = cu[mi][ni][0] + ub0;
            h0 = g * (u / (1.f + expf(-u)));
            g = cg[mi][ni][1] + gb1; u = cu[mi][ni][1] + ub1;
            h1 = g * (u / (1.f + expf(-u)));
            *(half2*)(g_H + (size_t)r0 * HID + n0 + col) = __floats2half2_rn(h0, h1);
            g = cg[mi][ni][2] + gb0; u = cu[mi][ni][2] + ub0;
            h0 = g * (u / (1.f + expf(-u)));
            g = cg[mi][ni][3] + gb1; u = cu[mi][ni][3] + ub1;
            h1 = g * (u / (1.f + expf(-u)));
            *(half2*)(g_H + (size_t)(r0 + 8) * HID + n0 + col) = __floats2half2_rn(h0, h1);
        }
    }
}

// ============ FFN stage 2: Y = H @ dp_w, fp16 mma ============
__global__ void __launch_bounds__(256, 2)
ffn2_mma() {
    int mt = blockIdx.x;
    int e = g_tile_e[mt];
    if (e < 0) return;
    int rb = g_tile_base[mt];
    int n0 = blockIdx.y * BNT;

    extern __shared__ uint32_t sm2[];

    int tid = threadIdx.x, lane = tid & 31, wid = tid >> 5;
    uint32_t sbase = smem_u32(sm2);
    const __half* dpe = g_dph + (size_t)e * DM * HID;   // [n][k]

    const __half* asrc[2]; const __half* bsrc[2]; uint32_t tdst[2];
#pragma unroll
    for (int j = 0; j < 2; j++) {
        int p = tid + 256 * j;
        int row = p >> 2, pc = p & 3;
        asrc[j] = g_H + (size_t)(rb + row) * HID + pc * 8;
        bsrc[j] = dpe + (size_t)(n0 + row) * HID + pc * 8;
        tdst[j] = (uint32_t)(row * TSTRIDE + pc * 4) * 4u;
    }

    float ca[2][8][4] = {};
    int mlane = (wid & 3) * 32 + (lane >> 2);
    int nbase = (wid >> 2) * 64 + (lane >> 2);
    int tig = lane & 3;

    const int NC = HID / BK;   // 16
#pragma unroll
    for (int pc = 0; pc < S2 - 1; pc++) {
        uint32_t stg = sbase + (uint32_t)(pc * F2_STAGE * 4);
        int k0 = pc * BK;
#pragma unroll
        for (int j = 0; j < 2; j++) {
            CP16(stg + tdst[j], asrc[j] + k0);
            CP16(stg + TILE_WORDS * 4 + tdst[j], bsrc[j] + k0);
        }
        CP_COMMIT();
    }

    for (int c = 0; c < NC; ++c) {
        CP_WAIT(S2 - 2);
        __syncthreads();
        int cn = c + S2 - 1;
        if (cn < NC) {
            int k0 = cn * BK;
            uint32_t stg = sbase + (uint32_t)((cn % S2) * F2_STAGE * 4);
#pragma unroll
            for (int j = 0; j < 2; j++) {
                CP16(stg + tdst[j], asrc[j] + k0);
                CP16(stg + TILE_WORDS * 4 + tdst[j], bsrc[j] + k0);
            }
        }
        CP_COMMIT();
        const uint32_t* A = sm2 + (c % S2) * F2_STAGE;
        const uint32_t* B = A + TILE_WORDS;
#pragma unroll
        for (int s = 0; s < 2; s++) {
            int ks = 8 * s + tig;
            uint32_t a[2][4];
#pragma unroll
            for (int mi = 0; mi < 2; mi++) {
                int m = mlane + mi * 16;
                a[mi][0] = A[m * TSTRIDE + ks];
                a[mi][1] = A[(m + 8) * TSTRIDE + ks];
                a[mi][2] = A[m * TSTRIDE + ks + 4];
                a[mi][3] = A[(m + 8) * TSTRIDE + ks + 4];
            }
#pragma unroll
            for (int ni = 0; ni < 8; ni++) {
                int n = nbase + ni * 8;
                uint32_t b0 = B[n * TSTRIDE + ks], b1 = B[n * TSTRIDE + ks + 4];
                mma16(ca[0][ni], a[0], b0, b1);
                mma16(ca[1][ni], a[1], b0, b1);
            }
        }
    }

    int rrow = rb + (wid & 3) * 32 + (lane >> 2);
    int cbase = (wid >> 2) * 64 + 2 * (lane & 3);
#pragma unroll
    for (int ni = 0; ni < 8; ni++) {
        int col = n0 + cbase + ni * 8;
#pragma unroll
        for (int mi = 0; mi < 2; mi++) {
            int r0 = rrow + mi * 16;
            *(float2*)(g_Y + (size_t)r0 * DM + col) =
                make_float2(ca[mi][ni][0], ca[mi][ni][1]);
            *(float2*)(g_Y + (size_t)(r0 + 8) * DM + col) =
                make_float2(ca[mi][ni][2], ca[mi][ni][3]);
        }
    }
}

// combine: out[t] = w1*(Y[p1]+b_e1) + w2*(Y[p2]+b_e2)
__global__ void __launch_bounds__(256)
combine_kernel(const float* __restrict__ dp_b, float* __restrict__ out) {
    int t = blockIdx.x;
    int c = threadIdx.x;
    int e1 = g_tok_idx[2 * t], e2 = g_tok_idx[2 * t + 1];
    float w1 = g_tok_w[2 * t], w2 = g_tok_w[2 * t + 1];
    int p1 = g_tok_pos[2 * t], p2 = g_tok_pos[2 * t + 1];
    float4 y1 = ((const float4*)(g_Y + (size_t)p1 * DM))[c];
    float4 y2 = ((const float4*)(g_Y + (size_t)p2 * DM))[c];
    float4 b1 = ((const float4*)(dp_b + (size_t)e1 * DM))[c];
    float4 b2 = ((const float4*)(dp_b + (size_t)e2 * DM))[c];
    float4 r;
    r.x = w1 * (y1.x + b1.x) + w2 * (y2.x + b2.x);
    r.y = w1 * (y1.y + b1.y) + w2 * (y2.y + b2.y);
    r.z = w1 * (y1.z + b1.z) + w2 * (y2.z + b2.z);
    r.w = w1 * (y1.w + b1.w) + w2 * (y2.w + b2.w);
    ((float4*)out)[(size_t)t * (DM / 4) + c] = r;
}

// ---------------- launcher ----------------
extern "C" void kernel_launch(void* const* d_in, const int* in_sizes, int n_in,
                              void* d_out, int out_size) {
    const float* x   = (const float*)d_in[0];
    const float* gw  = (const float*)d_in[1];
    const float* gb  = (const float*)d_in[2];
    const float* gpw = (const float*)d_in[3];
    const float* gpb = (const float*)d_in[4];
    const float* upw = (const float*)d_in[5];
    const float* upb = (const float*)d_in[6];
    const float* dpw = (const float*)d_in[7];
    const float* dpb = (const float*)d_in[8];
    float* out = (float*)d_out;

    static int attr_done = 0;
    if (!attr_done) {
        cudaFuncSetAttribute(ffn1_mma, cudaFuncAttributeMaxDynamicSharedMemorySize,
                             F1_SMEM);
        cudaFuncSetAttribute(ffn2_mma, cudaFuncAttributeMaxDynamicSharedMemorySize,
                             F2_SMEM);
        attr_done = 1;
    }

    init_kernel<<<1, 32>>>();
    gate_kernel<<<(T_TOK * 32 + 255) / 256, 256>>>(x, gw, gb);
    scan_kernel<<<1, 1>>>();
    scatter_kernel<<<(T_TOK + 255) / 256, 256>>>();

    __half* gph; cudaGetSymbolAddress((void**)&gph, g_gph);
    __half* uph; cudaGetSymbolAddress((void**)&uph, g_uph);
    __half* dph; cudaGetSymbolAddress((void**)&dph, g_dph);
    transpose_w<<<dim3(HID / 32, DM / 32, NE), dim3(32, 8)>>>(gpw, gph, DM, HID);
    transpose_w<<<dim3(HID / 32, DM / 32, NE), dim3(32, 8)>>>(upw, uph, DM, HID);
    transpose_w<<<dim3(DM / 32, HID / 32, NE), dim3(32, 8)>>>(dpw, dph, HID, DM);

    aux_kernel<<<1, 32>>>(out, (long)out_size);

    ffn1_mma<<<dim3(MTILES, HID / BNT), 256, F1_SMEM>>>(gpb, upb);
    ffn2_mma<<<dim3(MTILES, DM / BNT), 256, F2_SMEM>>>();
    combine_kernel<<<T_TOK, 256>>>(dpb, out);
}

// round 13
// speedup vs baseline: 3.1782x; 1.0494x over previous
#include <cuda_runtime.h>
#include <cuda_fp16.h>
#include <math.h>
#include <stdint.h>

// ---------------- problem constants ----------------
#define T_TOK 16384
#define DM    1024
#define HID   512
#define NE    16
#define TOPK  2

// ---------------- tiling ----------------
#define BMT 128
#define BNT 128
#define BK  32                         // k-halves per pipeline chunk
#define MTILES 272
#define PAD_ROWS (MTILES * BMT)

#define TSTRIDE 20                     // words per tile row (16 data + 4 pad)
#define ROWB (TSTRIDE * 4)             // 80 bytes per row
#define TILE_WORDS (128 * TSTRIDE)     // 2560 words per 128x32-half tile
#define F1_STAGE (3 * TILE_WORDS)      // A + G + U = 7680 words
#define F2_STAGE (2 * TILE_WORDS)      // A + B = 5120 words
#define S1 4
#define S2 3
#define F1_SMEM (S1 * F1_STAGE * 4)    // 122880 B
#define F2_SMEM (S2 * F2_STAGE * 4)    // 61440 B

// ---------------- static scratch ----------------
__device__ int   g_counts[NE];
__device__ int   g_cursor[NE];
__device__ int   g_off[NE];
__device__ int   g_tile_e[MTILES];
__device__ int   g_tile_base[MTILES];
__device__ int   g_tok_idx[T_TOK * TOPK];
__device__ float g_tok_w[T_TOK * TOPK];
__device__ int   g_row_tok[PAD_ROWS];
__device__ float g_row_w[PAD_ROWS];
__device__ __align__(16) __half g_Xh[(size_t)T_TOK * DM];
__device__ __align__(16) __half g_gph[(size_t)NE * HID * DM];   // [e][n][k]
__device__ __align__(16) __half g_uph[(size_t)NE * HID * DM];   // [e][n][k]
__device__ __align__(16) __half g_dph[(size_t)NE * DM * HID];   // [e][n][k]
__device__ __align__(16) __half g_H[(size_t)PAD_ROWS * HID];

// ---------------- helpers ----------------
__device__ __forceinline__ uint32_t smem_u32(const void* p) {
    uint32_t a;
    asm("{ .reg .u64 t; cvta.to.shared.u64 t, %1; cvt.u32.u64 %0, t; }" : "=r"(a) : "l"(p));
    return a;
}

__device__ __forceinline__ void mma16(float c[4], const uint32_t a[4],
                                      uint32_t b0, uint32_t b1) {
    asm volatile(
        "mma.sync.aligned.m16n8k16.row.col.f32.f16.f16.f32 "
        "{%0,%1,%2,%3}, {%4,%5,%6,%7}, {%8,%9}, {%0,%1,%2,%3};"
        : "+f"(c[0]), "+f"(c[1]), "+f"(c[2]), "+f"(c[3])
        : "r"(a[0]), "r"(a[1]), "r"(a[2]), "r"(a[3]), "r"(b0), "r"(b1));
}

__device__ __forceinline__ void ldsm4(uint32_t r[4], uint32_t addr) {
    asm volatile("ldmatrix.sync.aligned.m8n8.x4.shared.b16 {%0,%1,%2,%3}, [%4];"
                 : "=r"(r[0]), "=r"(r[1]), "=r"(r[2]), "=r"(r[3]) : "r"(addr));
}

#define CP16(dst, src) \
    asm volatile("cp.async.cg.shared.global [%0], [%1], 16;" :: "r"(dst), "l"(src))
#define CP16Z(dst, src, sz) \
    asm volatile("cp.async.cg.shared.global [%0], [%1], 16, %2;" :: "r"(dst), "l"(src), "r"(sz))
#define CP_COMMIT() asm volatile("cp.async.commit_group;" ::: "memory")
#define CP_WAIT(n)  asm volatile("cp.async.wait_group %0;" :: "n"(n) : "memory")

// ---------------- routing kernels ----------------
__global__ void init_kernel() {
    int i = threadIdx.x;
    if (i < NE) g_counts[i] = 0;
}

// gate + fused fp16 conversion of x into g_Xh
__global__ void gate_kernel(const float* __restrict__ x,
                            const float* __restrict__ gw,
                            const float* __restrict__ gb) {
    int gid = blockIdx.x * blockDim.x + threadIdx.x;
    int t = gid >> 5, lane = gid & 31;
    if (t >= T_TOK) return;
    const float* xr = x + (size_t)t * DM;
    __half* xo = g_Xh + (size_t)t * DM;
    float acc[NE];
#pragma unroll
    for (int e = 0; e < NE; e++) acc[e] = 0.f;
    for (int d = lane; d < DM; d += 32) {
        float xv = xr[d];
        xo[d] = __float2half_rn(xv);
        const float* g = gw + d * NE;
#pragma unroll
        for (int e = 0; e < NE; e++) acc[e] = fmaf(xv, g[e], acc[e]);
    }
#pragma unroll
    for (int e = 0; e < NE; e++)
#pragma unroll
        for (int o = 16; o > 0; o >>= 1)
            acc[e] += __shfl_xor_sync(0xffffffffu, acc[e], o);
    if (lane == 0) {
        float s[NE], mx = -1e30f;
#pragma unroll
        for (int e = 0; e < NE; e++) { s[e] = acc[e] + gb[e]; mx = fmaxf(mx, s[e]); }
        float sum = 0.f;
#pragma unroll
        for (int e = 0; e < NE; e++) { s[e] = expf(s[e] - mx); sum += s[e]; }
        int i1 = 0; float v1 = -1.f;
#pragma unroll
        for (int e = 0; e < NE; e++) if (s[e] > v1) { v1 = s[e]; i1 = e; }
        int i2 = 0; float v2 = -1.f;
#pragma unroll
        for (int e = 0; e < NE; e++) if (e != i1 && s[e] > v2) { v2 = s[e]; i2 = e; }
        float p1 = v1 / sum, p2 = v2 / sum;
        float den = p1 + p2 + 1e-9f;
        g_tok_idx[2 * t + 0] = i1; g_tok_w[2 * t + 0] = p1 / den;
        g_tok_idx[2 * t + 1] = i2; g_tok_w[2 * t + 1] = p2 / den;
        atomicAdd(&g_counts[i1], 1);
        atomicAdd(&g_counts[i2], 1);
    }
}

__global__ void scan_kernel() {
    int off = 0, tile = 0;
    for (int e = 0; e < NE; e++) {
        g_off[e] = off; g_cursor[e] = 0;
        int c = g_counts[e];
        int nt = (c + BMT - 1) / BMT;
        for (int j = 0; j < nt; j++) {
            g_tile_e[tile] = e;
            g_tile_base[tile] = off + j * BMT;
            tile++;
        }
        for (int r = off + c; r < off + nt * BMT; r++) {
            g_row_tok[r] = -1;
            g_row_w[r] = 0.f;
        }
        off += nt * BMT;
    }
    for (; tile < MTILES; tile++) g_tile_e[tile] = -1;
}

__global__ void scatter_kernel() {
    int t = blockIdx.x * blockDim.x + threadIdx.x;
    if (t >= T_TOK) return;
#pragma unroll
    for (int k = 0; k < TOPK; k++) {
        int e = g_tok_idx[2 * t + k];
        int pos = g_off[e] + atomicAdd(&g_cursor[e], 1);
        g_row_tok[pos] = t;
        g_row_w[pos] = g_tok_w[2 * t + k];
    }
}

__global__ void zero_kernel(float* out, long n) {
    long i = blockIdx.x * (long)blockDim.x + threadIdx.x;
    long st = (long)gridDim.x * blockDim.x;
    for (; i < n; i += st) out[i] = 0.f;
}

__global__ void aux_kernel(float* out, long out_size) {
    if (blockIdx.x == 0 && threadIdx.x == 0) {
        const float cap = 1.25f * (float)(T_TOK * TOPK) / (float)NE;
        float sum = 0.f;
        for (int e = 0; e < NE; e++) {
            float l = (float)g_counts[e] - cap;
            if (l > 0.f) sum += l;
        }
        float aux = 0.01f * sum / (float)NE / (float)T_TOK;
        long TD = (long)T_TOK * DM;
        if (out_size > TD) out[TD] = aux;
    }
}

// weights [e][K][N] float -> [e][N][K] half
__global__ void transpose_w(const float* __restrict__ src, __half* __restrict__ dst,
                            int K, int N) {
    __shared__ float tile[32][33];
    int e = blockIdx.z;
    int k0 = blockIdx.y * 32, n0 = blockIdx.x * 32;
    src += (size_t)e * K * N;
    dst += (size_t)e * K * N;
    int tx = threadIdx.x, ty = threadIdx.y;
#pragma unroll
    for (int i = 0; i < 32; i += 8)
        tile[ty + i][tx] = src[(size_t)(k0 + ty + i) * N + n0 + tx];
    __syncthreads();
#pragma unroll
    for (int i = 0; i < 32; i += 8)
        dst[(size_t)(n0 + ty + i) * K + k0 + tx] = __float2half_rn(tile[tx][ty + i]);
}

// ============ FFN stage 1: H = (X@gp + b) * silu(X@up + b), fp16 mma ============
__global__ void __launch_bounds__(256)
ffn1_mma(const float* __restrict__ gp_b, const float* __restrict__ up_b) {
    int mt = blockIdx.x;
    int e = g_tile_e[mt];
    if (e < 0) return;
    int rb = g_tile_base[mt];
    int n0 = blockIdx.y * BNT;

    extern __shared__ uint32_t sm[];
    __shared__ int s_toks[BMT];

    int tid = threadIdx.x, lane = tid & 31, wid = tid >> 5;
    if (tid < BMT) s_toks[tid] = g_row_tok[rb + tid];
    __syncthreads();

    uint32_t sbase = smem_u32(sm);
    const __half* gpe = g_gph + (size_t)e * HID * DM;   // [n][k]
    const __half* upe = g_uph + (size_t)e * HID * DM;

    const __half* asrc[2]; uint32_t asz[2], tdst[2];
    const __half* gsrc[2]; const __half* usrc[2];
#pragma unroll
    for (int j = 0; j < 2; j++) {
        int p = tid + 256 * j;
        int row = p >> 2, pc = p & 3;
        int tok = s_toks[row];
        asrc[j] = g_Xh + (size_t)(tok >= 0 ? tok : 0) * DM + pc * 8;
        asz[j]  = (tok >= 0) ? 16u : 0u;
        gsrc[j] = gpe + (size_t)(n0 + row) * DM + pc * 8;
        usrc[j] = upe + (size_t)(n0 + row) * DM + pc * 8;
        tdst[j] = (uint32_t)(row * TSTRIDE + pc * 4) * 4u;
    }

    float cg[2][8][4] = {}, cu[2][8][4] = {};
    // ldmatrix lane offsets (bytes within tile)
    uint32_t a_off = (uint32_t)(((wid & 3) * 32 + (lane & 15)) * ROWB + (lane >> 4) * 16);
    uint32_t b_off = (uint32_t)(((wid >> 2) * 64 + ((lane >> 4) & 1) * 8 + (lane & 7)) * ROWB
                                + ((lane >> 3) & 1) * 16);

    const int NC = DM / BK;   // 32
#pragma unroll
    for (int pc = 0; pc < S1 - 1; pc++) {
        uint32_t stg = sbase + (uint32_t)(pc * F1_STAGE * 4);
        int k0 = pc * BK;
#pragma unroll
        for (int j = 0; j < 2; j++) {
            CP16Z(stg + tdst[j], asrc[j] + k0, asz[j]);
            CP16(stg + TILE_WORDS * 4 + tdst[j], gsrc[j] + k0);
            CP16(stg + 2 * TILE_WORDS * 4 + tdst[j], usrc[j] + k0);
        }
        CP_COMMIT();
    }

    for (int c = 0; c < NC; ++c) {
        CP_WAIT(S1 - 2);
        __syncthreads();
        int cn = c + S1 - 1;
        if (cn < NC) {
            int k0 = cn * BK;
            uint32_t stg = sbase + (uint32_t)((cn & (S1 - 1)) * F1_STAGE * 4);
#pragma unroll
            for (int j = 0; j < 2; j++) {
                CP16Z(stg + tdst[j], asrc[j] + k0, asz[j]);
                CP16(stg + TILE_WORDS * 4 + tdst[j], gsrc[j] + k0);
                CP16(stg + 2 * TILE_WORDS * 4 + tdst[j], usrc[j] + k0);
            }
        }
        CP_COMMIT();
        uint32_t Ab = sbase + (uint32_t)((c & (S1 - 1)) * F1_STAGE * 4);
        uint32_t Gb = Ab + TILE_WORDS * 4;
        uint32_t Ub = Gb + TILE_WORDS * 4;
#pragma unroll
        for (int s = 0; s < 2; s++) {          // two k16 slices per chunk
            uint32_t so = (uint32_t)(s * 32);  // 16 halves
            uint32_t a[2][4], gf[4][4], uf[4][4];
#pragma unroll
            for (int mi = 0; mi < 2; mi++)
                ldsm4(a[mi], Ab + a_off + (uint32_t)(mi * 16 * ROWB) + so);
#pragma unroll
            for (int pi = 0; pi < 4; pi++) {
                ldsm4(gf[pi], Gb + b_off + (uint32_t)(pi * 16 * ROWB) + so);
                ldsm4(uf[pi], Ub + b_off + (uint32_t)(pi * 16 * ROWB) + so);
            }
#pragma unroll
            for (int pi = 0; pi < 4; pi++) {
#pragma unroll
                for (int h = 0; h < 2; h++) {
                    int ni = 2 * pi + h;
                    uint32_t g0 = gf[pi][2 * h], g1 = gf[pi][2 * h + 1];
                    uint32_t u0 = uf[pi][2 * h], u1 = uf[pi][2 * h + 1];
                    mma16(cg[0][ni], a[0], g0, g1);
                    mma16(cg[1][ni], a[1], g0, g1);
                    mma16(cu[0][ni], a[0], u0, u1);
                    mma16(cu[1][ni], a[1], u0, u1);
                }
            }
        }
    }

    // epilogue: h = (g + gpb) * silu(u + upb) -> g_H (fp16)
    const float* gpb = gp_b + e * HID + n0;
    const float* upb = up_b + e * HID + n0;
    int rrow = rb + (wid & 3) * 32 + (lane >> 2);
    int cbase = (wid >> 2) * 64 + 2 * (lane & 3);
#pragma unroll
    for (int ni = 0; ni < 8; ni++) {
        int col = cbase + ni * 8;
        float gb0 = gpb[col], gb1 = gpb[col + 1];
        float ub0 = upb[col], ub1 = upb[col + 1];
#pragma unroll
        for (int mi = 0; mi < 2; mi++) {
            int r0 = rrow + mi * 16;
            float g, u, h0, h1;
            g = cg[mi][ni][0] + gb0; u = cu[mi][ni][0] + ub0;
            h0 = g * (u / (1.f + expf(-u)));
            g = cg[mi][ni][1] + gb1; u = cu[mi][ni][1] + ub1;
            h1 = g * (u / (1.f + expf(-u)));
            *(half2*)(g_H + (size_t)r0 * HID + n0 + col) = __floats2half2_rn(h0, h1);
            g = cg[mi][ni][2] + gb0; u = cu[mi][ni][2] + ub0;
            h0 = g * (u / (1.f + expf(-u)));
            g = cg[mi][ni][3] + gb1; u = cu[mi][ni][3] + ub1;
            h1 = g * (u / (1.f + expf(-u)));
            *(half2*)(g_H + (size_t)(r0 + 8) * HID + n0 + col) = __floats2half2_rn(h0, h1);
        }
    }
}

// ============ FFN stage 2: out[tok] += w * (H @ dp_w + dp_b), fp16 mma ============
__global__ void __launch_bounds__(256, 2)
ffn2_mma(const float* __restrict__ dp_b, float* __restrict__ out) {
    int mt = blockIdx.x;
    int e = g_tile_e[mt];
    if (e < 0) return;
    int rb = g_tile_base[mt];
    int n0 = blockIdx.y * BNT;

    extern __shared__ uint32_t sm2[];
    __shared__ int   s_toks[BMT];
    __shared__ float s_wts[BMT];

    int tid = threadIdx.x, lane = tid & 31, wid = tid >> 5;
    if (tid < BMT) {
        s_toks[tid] = g_row_tok[rb + tid];
        s_wts[tid]  = g_row_w[rb + tid];
    }
    __syncthreads();

    uint32_t sbase = smem_u32(sm2);
    const __half* dpe = g_dph + (size_t)e * DM * HID;   // [n][k]

    const __half* asrc[2]; const __half* bsrc[2]; uint32_t tdst[2];
#pragma unroll
    for (int j = 0; j < 2; j++) {
        int p = tid + 256 * j;
        int row = p >> 2, pc = p & 3;
        asrc[j] = g_H + (size_t)(rb + row) * HID + pc * 8;
        bsrc[j] = dpe + (size_t)(n0 + row) * HID + pc * 8;
        tdst[j] = (uint32_t)(row * TSTRIDE + pc * 4) * 4u;
    }

    float ca[2][8][4] = {};
    uint32_t a_off = (uint32_t)(((wid & 3) * 32 + (lane & 15)) * ROWB + (lane >> 4) * 16);
    uint32_t b_off = (uint32_t)(((wid >> 2) * 64 + ((lane >> 4) & 1) * 8 + (lane & 7)) * ROWB
                                + ((lane >> 3) & 1) * 16);

    const int NC = HID / BK;   // 16
#pragma unroll
    for (int pc = 0; pc < S2 - 1; pc++) {
        uint32_t stg = sbase + (uint32_t)(pc * F2_STAGE * 4);
        int k0 = pc * BK;
#pragma unroll
        for (int j = 0; j < 2; j++) {
            CP16(stg + tdst[j], asrc[j] + k0);
            CP16(stg + TILE_WORDS * 4 + tdst[j], bsrc[j] + k0);
        }
        CP_COMMIT();
    }

    for (int c = 0; c < NC; ++c) {
        CP_WAIT(S2 - 2);
        __syncthreads();
        int cn = c + S2 - 1;
        if (cn < NC) {
            int k0 = cn * BK;
            uint32_t stg = sbase + (uint32_t)((cn % S2) * F2_STAGE * 4);
#pragma unroll
            for (int j = 0; j < 2; j++) {
                CP16(stg + tdst[j], asrc[j] + k0);
                CP16(stg + TILE_WORDS * 4 + tdst[j], bsrc[j] + k0);
            }
        }
        CP_COMMIT();
        uint32_t Ab = sbase + (uint32_t)((c % S2) * F2_STAGE * 4);
        uint32_t Bb = Ab + TILE_WORDS * 4;
#pragma unroll
        for (int s = 0; s < 2; s++) {
            uint32_t so = (uint32_t)(s * 32);
            uint32_t a[2][4], bf[4][4];
#pragma unroll
            for (int mi = 0; mi < 2; mi++)
                ldsm4(a[mi], Ab + a_off + (uint32_t)(mi * 16 * ROWB) + so);
#pragma unroll
            for (int pi = 0; pi < 4; pi++)
                ldsm4(bf[pi], Bb + b_off + (uint32_t)(pi * 16 * ROWB) + so);
#pragma unroll
            for (int pi = 0; pi < 4; pi++) {
#pragma unroll
                for (int h = 0; h < 2; h++) {
                    int ni = 2 * pi + h;
                    mma16(ca[0][ni], a[0], bf[pi][2 * h], bf[pi][2 * h + 1]);
                    mma16(ca[1][ni], a[1], bf[pi][2 * h], bf[pi][2 * h + 1]);
                }
            }
        }
    }

    // epilogue: deterministic atomic combine (each out element gets exactly
    // TOPK commutative adds onto a zeroed base)
    const float* dpb = dp_b + e * DM;
    int lr = (wid & 3) * 32 + (lane >> 2);
    int cbase = (wid >> 2) * 64 + 2 * (lane & 3);
#pragma unroll
    for (int ni = 0; ni < 8; ni++) {
        int col = n0 + cbase + ni * 8;
        float b0v = dpb[col], b1v = dpb[col + 1];
#pragma unroll
        for (int mi = 0; mi < 2; mi++) {
            int l0 = lr + mi * 16;
            int t0 = s_toks[l0];
            if (t0 >= 0) {
                float w = s_wts[l0];
                atomicAdd(out + (size_t)t0 * DM + col,     w * (ca[mi][ni][0] + b0v));
                atomicAdd(out + (size_t)t0 * DM + col + 1, w * (ca[mi][ni][1] + b1v));
            }
            int t1 = s_toks[l0 + 8];
            if (t1 >= 0) {
                float w = s_wts[l0 + 8];
                atomicAdd(out + (size_t)t1 * DM + col,     w * (ca[mi][ni][2] + b0v));
                atomicAdd(out + (size_t)t1 * DM + col + 1, w * (ca[mi][ni][3] + b1v));
            }
        }
    }
}

// ---------------- launcher ----------------
extern "C" void kernel_launch(void* const* d_in, const int* in_sizes, int n_in,
                              void* d_out, int out_size) {
    const float* x   = (const float*)d_in[0];
    const float* gw  = (const float*)d_in[1];
    const float* gb  = (const float*)d_in[2];
    const float* gpw = (const float*)d_in[3];
    const float* gpb = (const float*)d_in[4];
    const float* upw = (const float*)d_in[5];
    const float* upb = (const float*)d_in[6];
    const float* dpw = (const float*)d_in[7];
    const float* dpb = (const float*)d_in[8];
    float* out = (float*)d_out;

    static int attr_done = 0;
    if (!attr_done) {
        cudaFuncSetAttribute(ffn1_mma, cudaFuncAttributeMaxDynamicSharedMemorySize,
                             F1_SMEM);
        cudaFuncSetAttribute(ffn2_mma, cudaFuncAttributeMaxDynamicSharedMemorySize,
                             F2_SMEM);
        attr_done = 1;
    }

    init_kernel<<<1, 32>>>();
    gate_kernel<<<(T_TOK * 32 + 255) / 256, 256>>>(x, gw, gb);
    scan_kernel<<<1, 1>>>();
    scatter_kernel<<<(T_TOK + 255) / 256, 256>>>();

    __half* gph; cudaGetSymbolAddress((void**)&gph, g_gph);
    __half* uph; cudaGetSymbolAddress((void**)&uph, g_uph);
    __half* dph; cudaGetSymbolAddress((void**)&dph, g_dph);
    transpose_w<<<dim3(HID / 32, DM / 32, NE), dim3(32, 8)>>>(gpw, gph, DM, HID);
    transpose_w<<<dim3(HID / 32, DM / 32, NE), dim3(32, 8)>>>(upw, uph, DM, HID);
    transpose_w<<<dim3(DM / 32, HID / 32, NE), dim3(32, 8)>>>(dpw, dph, HID, DM);

    zero_kernel<<<1024, 256>>>(out, (long)out_size);
    aux_kernel<<<1, 32>>>(out, (long)out_size);

    ffn1_mma<<<dim3(MTILES, HID / BNT), 256, F1_SMEM>>>(gpb, upb);
    ffn2_mma<<<dim3(MTILES, DM / BNT), 256, F2_SMEM>>>(dpb, out);
}

// round 14
// speedup vs baseline: 3.2235x; 1.0143x over previous
#include <cuda_runtime.h>
#include <cuda_fp16.h>
#include <math.h>
#include <stdint.h>

// ---------------- problem constants ----------------
#define T_TOK 16384
#define DM    1024
#define HID   512
#define NE    16
#define TOPK  2

// ---------------- tiling ----------------
#define BMT 128
#define BNT 128
#define BK  32                         // k-halves per pipeline chunk
#define MTILES 272
#define PAD_ROWS (MTILES * BMT)

#define TSTRIDE 20                     // words per tile row (16 data + 4 pad)
#define ROWB (TSTRIDE * 4)             // 80 bytes per row
#define TILE_WORDS (128 * TSTRIDE)     // 2560 words per 128x32-half tile
#define F1_STAGE (3 * TILE_WORDS)      // A + G + U = 7680 words
#define F2_STAGE (2 * TILE_WORDS)      // A + B = 5120 words
#define S1 3
#define S2 3
#define F1_SMEM (S1 * F1_STAGE * 4)    // 92160 B
#define F2_SMEM (S2 * F2_STAGE * 4)    // 61440 B

// ---------------- static scratch ----------------
__device__ int   g_counts[NE];
__device__ int   g_cursor[NE];
__device__ int   g_off[NE];
__device__ int   g_tile_e[MTILES];
__device__ int   g_tile_base[MTILES];
__device__ int   g_tok_idx[T_TOK * TOPK];
__device__ float g_tok_w[T_TOK * TOPK];
__device__ int   g_row_tok[PAD_ROWS];
__device__ float g_row_w[PAD_ROWS];
__device__ __align__(16) __half g_Xh[(size_t)T_TOK * DM];
__device__ __align__(16) __half g_gph[(size_t)NE * HID * DM];   // [e][n][k]
__device__ __align__(16) __half g_uph[(size_t)NE * HID * DM];   // [e][n][k]
__device__ __align__(16) __half g_dph[(size_t)NE * DM * HID];   // [e][n][k]
__device__ __align__(16) __half g_H[(size_t)PAD_ROWS * HID];

// ---------------- helpers ----------------
__device__ __forceinline__ uint32_t smem_u32(const void* p) {
    uint32_t a;
    asm("{ .reg .u64 t; cvta.to.shared.u64 t, %1; cvt.u32.u64 %0, t; }" : "=r"(a) : "l"(p));
    return a;
}

__device__ __forceinline__ void mma16(float c[4], const uint32_t a[4],
                                      uint32_t b0, uint32_t b1) {
    asm volatile(
        "mma.sync.aligned.m16n8k16.row.col.f32.f16.f16.f32 "
        "{%0,%1,%2,%3}, {%4,%5,%6,%7}, {%8,%9}, {%0,%1,%2,%3};"
        : "+f"(c[0]), "+f"(c[1]), "+f"(c[2]), "+f"(c[3])
        : "r"(a[0]), "r"(a[1]), "r"(a[2]), "r"(a[3]), "r"(b0), "r"(b1));
}

__device__ __forceinline__ void ldsm4(uint32_t r[4], uint32_t addr) {
    asm volatile("ldmatrix.sync.aligned.m8n8.x4.shared.b16 {%0,%1,%2,%3}, [%4];"
                 : "=r"(r[0]), "=r"(r[1]), "=r"(r[2]), "=r"(r[3]) : "r"(addr));
}

#define CP16(dst, src) \
    asm volatile("cp.async.cg.shared.global [%0], [%1], 16;" :: "r"(dst), "l"(src))
#define CP16Z(dst, src, sz) \
    asm volatile("cp.async.cg.shared.global [%0], [%1], 16, %2;" :: "r"(dst), "l"(src), "r"(sz))
#define CP_COMMIT() asm volatile("cp.async.commit_group;" ::: "memory")
#define CP_WAIT(n)  asm volatile("cp.async.wait_group %0;" :: "n"(n) : "memory")

// ---------------- routing kernels ----------------
__global__ void init_kernel() {
    int i = threadIdx.x;
    if (i < NE) g_counts[i] = 0;
}

// gate + fused fp16 conversion of x into g_Xh
__global__ void gate_kernel(const float* __restrict__ x,
                            const float* __restrict__ gw,
                            const float* __restrict__ gb) {
    int gid = blockIdx.x * blockDim.x + threadIdx.x;
    int t = gid >> 5, lane = gid & 31;
    if (t >= T_TOK) return;
    const float* xr = x + (size_t)t * DM;
    __half* xo = g_Xh + (size_t)t * DM;
    float acc[NE];
#pragma unroll
    for (int e = 0; e < NE; e++) acc[e] = 0.f;
    for (int d = lane; d < DM; d += 32) {
        float xv = xr[d];
        xo[d] = __float2half_rn(xv);
        const float* g = gw + d * NE;
#pragma unroll
        for (int e = 0; e < NE; e++) acc[e] = fmaf(xv, g[e], acc[e]);
    }
#pragma unroll
    for (int e = 0; e < NE; e++)
#pragma unroll
        for (int o = 16; o > 0; o >>= 1)
            acc[e] += __shfl_xor_sync(0xffffffffu, acc[e], o);
    if (lane == 0) {
        float s[NE], mx = -1e30f;
#pragma unroll
        for (int e = 0; e < NE; e++) { s[e] = acc[e] + gb[e]; mx = fmaxf(mx, s[e]); }
        float sum = 0.f;
#pragma unroll
        for (int e = 0; e < NE; e++) { s[e] = expf(s[e] - mx); sum += s[e]; }
        int i1 = 0; float v1 = -1.f;
#pragma unroll
        for (int e = 0; e < NE; e++) if (s[e] > v1) { v1 = s[e]; i1 = e; }
        int i2 = 0; float v2 = -1.f;
#pragma unroll
        for (int e = 0; e < NE; e++) if (e != i1 && s[e] > v2) { v2 = s[e]; i2 = e; }
        float p1 = v1 / sum, p2 = v2 / sum;
        float den = p1 + p2 + 1e-9f;
        g_tok_idx[2 * t + 0] = i1; g_tok_w[2 * t + 0] = p1 / den;
        g_tok_idx[2 * t + 1] = i2; g_tok_w[2 * t + 1] = p2 / den;
        atomicAdd(&g_counts[i1], 1);
        atomicAdd(&g_counts[i2], 1);
    }
}

__global__ void scan_kernel() {
    int off = 0, tile = 0;
    for (int e = 0; e < NE; e++) {
        g_off[e] = off; g_cursor[e] = 0;
        int c = g_counts[e];
        int nt = (c + BMT - 1) / BMT;
        for (int j = 0; j < nt; j++) {
            g_tile_e[tile] = e;
            g_tile_base[tile] = off + j * BMT;
            tile++;
        }
        for (int r = off + c; r < off + nt * BMT; r++) {
            g_row_tok[r] = -1;
            g_row_w[r] = 0.f;
        }
        off += nt * BMT;
    }
    for (; tile < MTILES; tile++) g_tile_e[tile] = -1;
}

__global__ void scatter_kernel() {
    int t = blockIdx.x * blockDim.x + threadIdx.x;
    if (t >= T_TOK) return;
#pragma unroll
    for (int k = 0; k < TOPK; k++) {
        int e = g_tok_idx[2 * t + k];
        int pos = g_off[e] + atomicAdd(&g_cursor[e], 1);
        g_row_tok[pos] = t;
        g_row_w[pos] = g_tok_w[2 * t + k];
    }
}

__global__ void zero_kernel(float* out, long n) {
    long i = blockIdx.x * (long)blockDim.x + threadIdx.x;
    long st = (long)gridDim.x * blockDim.x;
    for (; i < n; i += st) out[i] = 0.f;
}

__global__ void aux_kernel(float* out, long out_size) {
    if (blockIdx.x == 0 && threadIdx.x == 0) {
        const float cap = 1.25f * (float)(T_TOK * TOPK) / (float)NE;
        float sum = 0.f;
        for (int e = 0; e < NE; e++) {
            float l = (float)g_counts[e] - cap;
            if (l > 0.f) sum += l;
        }
        float aux = 0.01f * sum / (float)NE / (float)T_TOK;
        long TD = (long)T_TOK * DM;
        if (out_size > TD) out[TD] = aux;
    }
}

// all three weights: [e][K][N] float -> [e][N][K] half, one fused launch
__global__ void convert_weights(const float* __restrict__ gp,
                                const float* __restrict__ up,
                                const float* __restrict__ dp) {
    __shared__ float tile[32][33];
    int z = blockIdx.z;                // 0..3*NE-1
    const float* src; __half* dst; int K, N;
    if (z < NE)          { src = gp + (size_t)z * DM * HID;        dst = g_gph + (size_t)z * HID * DM;        K = DM;  N = HID; }
    else if (z < 2 * NE) { src = up + (size_t)(z - NE) * DM * HID; dst = g_uph + (size_t)(z - NE) * HID * DM; K = DM;  N = HID; }
    else                 { src = dp + (size_t)(z - 2 * NE) * HID * DM; dst = g_dph + (size_t)(z - 2 * NE) * DM * HID; K = HID; N = DM; }
    int k0 = blockIdx.y * 32, n0 = blockIdx.x * 32;
    if (k0 >= K || n0 >= N) return;
    int tx = threadIdx.x, ty = threadIdx.y;
#pragma unroll
    for (int i = 0; i < 32; i += 8)
        tile[ty + i][tx] = src[(size_t)(k0 + ty + i) * N + n0 + tx];
    __syncthreads();
#pragma unroll
    for (int i = 0; i < 32; i += 8)
        dst[(size_t)(n0 + ty + i) * K + k0 + tx] = __float2half_rn(tile[tx][ty + i]);
}

// ============ FFN stage 1: H = (X@gp + b) * silu(X@up + b) ============
// 512 threads, 16 warps in 4x4 layout, warp tile 32x32 (x2 operands)
__global__ void __launch_bounds__(512, 1)
ffn1_mma(const float* __restrict__ gp_b, const float* __restrict__ up_b) {
    int mt = blockIdx.x;
    int e = g_tile_e[mt];
    if (e < 0) return;
    int rb = g_tile_base[mt];
    int n0 = blockIdx.y * BNT;

    extern __shared__ uint32_t sm[];
    __shared__ int s_toks[BMT];

    int tid = threadIdx.x, lane = tid & 31, wid = tid >> 5;
    int wm = wid & 3, wn = wid >> 2;   // 4x4 warp grid
    if (tid < BMT) s_toks[tid] = g_row_tok[rb + tid];
    __syncthreads();

    uint32_t sbase = smem_u32(sm);
    const __half* gpe = g_gph + (size_t)e * HID * DM;   // [n][k]
    const __half* upe = g_uph + (size_t)e * HID * DM;

    // loader mapping: one 16B piece per tile per thread (512 pieces/tile)
    int row = tid >> 2, pc = tid & 3;
    int tok = s_toks[row];
    const __half* asrc = g_Xh + (size_t)(tok >= 0 ? tok : 0) * DM + pc * 8;
    uint32_t asz = (tok >= 0) ? 16u : 0u;
    const __half* gsrc = gpe + (size_t)(n0 + row) * DM + pc * 8;
    const __half* usrc = upe + (size_t)(n0 + row) * DM + pc * 8;
    uint32_t tdst = (uint32_t)(row * TSTRIDE + pc * 4) * 4u;

    float cg[2][4][4] = {}, cu[2][4][4] = {};
    uint32_t a_off = (uint32_t)((wm * 32 + (lane & 15)) * ROWB + (lane >> 4) * 16);
    uint32_t b_off = (uint32_t)((wn * 32 + ((lane >> 4) & 1) * 8 + (lane & 7)) * ROWB
                                + ((lane >> 3) & 1) * 16);

    const int NC = DM / BK;   // 32
#pragma unroll
    for (int pcs = 0; pcs < S1 - 1; pcs++) {
        uint32_t stg = sbase + (uint32_t)(pcs * F1_STAGE * 4);
        int k0 = pcs * BK;
        CP16Z(stg + tdst, asrc + k0, asz);
        CP16(stg + TILE_WORDS * 4 + tdst, gsrc + k0);
        CP16(stg + 2 * TILE_WORDS * 4 + tdst, usrc + k0);
        CP_COMMIT();
    }

    for (int c = 0; c < NC; ++c) {
        CP_WAIT(S1 - 2);
        __syncthreads();
        int cn = c + S1 - 1;
        if (cn < NC) {
            int k0 = cn * BK;
            uint32_t stg = sbase + (uint32_t)((cn % S1) * F1_STAGE * 4);
            CP16Z(stg + tdst, asrc + k0, asz);
            CP16(stg + TILE_WORDS * 4 + tdst, gsrc + k0);
            CP16(stg + 2 * TILE_WORDS * 4 + tdst, usrc + k0);
        }
        CP_COMMIT();
        uint32_t Ab = sbase + (uint32_t)((c % S1) * F1_STAGE * 4);
        uint32_t Gb = Ab + TILE_WORDS * 4;
        uint32_t Ub = Gb + TILE_WORDS * 4;
#pragma unroll
        for (int s = 0; s < 2; s++) {          // two k16 slices per chunk
            uint32_t so = (uint32_t)(s * 32);  // 16 halves
            uint32_t a[2][4], gf[2][4], uf[2][4];
#pragma unroll
            for (int mi = 0; mi < 2; mi++)
                ldsm4(a[mi], Ab + a_off + (uint32_t)(mi * 16 * ROWB) + so);
#pragma unroll
            for (int pi = 0; pi < 2; pi++) {
                ldsm4(gf[pi], Gb + b_off + (uint32_t)(pi * 16 * ROWB) + so);
                ldsm4(uf[pi], Ub + b_off + (uint32_t)(pi * 16 * ROWB) + so);
            }
#pragma unroll
            for (int pi = 0; pi < 2; pi++) {
#pragma unroll
                for (int h = 0; h < 2; h++) {
                    int ni = 2 * pi + h;
                    uint32_t g0 = gf[pi][2 * h], g1 = gf[pi][2 * h + 1];
                    uint32_t u0 = uf[pi][2 * h], u1 = uf[pi][2 * h + 1];
                    mma16(cg[0][ni], a[0], g0, g1);
                    mma16(cg[1][ni], a[1], g0, g1);
                    mma16(cu[0][ni], a[0], u0, u1);
                    mma16(cu[1][ni], a[1], u0, u1);
                }
            }
        }
    }

    // epilogue: h = (g + gpb) * silu(u + upb) -> g_H (fp16)
    const float* gpb = gp_b + e * HID + n0;
    const float* upb = up_b + e * HID + n0;
    int rrow = rb + wm * 32 + (lane >> 2);
    int cbase = wn * 32 + 2 * (lane & 3);
#pragma unroll
    for (int ni = 0; ni < 4; ni++) {
        int col = cbase + ni * 8;
        float gb0 = gpb[col], gb1 = gpb[col + 1];
        float ub0 = upb[col], ub1 = upb[col + 1];
#pragma unroll
        for (int mi = 0; mi < 2; mi++) {
            int r0 = rrow + mi * 16;
            float g, u, h0, h1;
            g = cg[mi][ni][0] + gb0; u = cu[mi][ni][0] + ub0;
            h0 = g * (u / (1.f + expf(-u)));
            g = cg[mi][ni][1] + gb1; u = cu[mi][ni][1] + ub1;
            h1 = g * (u / (1.f + expf(-u)));
            *(half2*)(g_H + (size_t)r0 * HID + n0 + col) = __floats2half2_rn(h0, h1);
            g = cg[mi][ni][2] + gb0; u = cu[mi][ni][2] + ub0;
            h0 = g * (u / (1.f + expf(-u)));
            g = cg[mi][ni][3] + gb1; u = cu[mi][ni][3] + ub1;
            h1 = g * (u / (1.f + expf(-u)));
            *(half2*)(g_H + (size_t)(r0 + 8) * HID + n0 + col) = __floats2half2_rn(h0, h1);
        }
    }
}

// ============ FFN stage 2: out[tok] += w * (H @ dp_w + dp_b), fp16 mma ============
__global__ void __launch_bounds__(256, 2)
ffn2_mma(const float* __restrict__ dp_b, float* __restrict__ out) {
    int mt = blockIdx.x;
    int e = g_tile_e[mt];
    if (e < 0) return;
    int rb = g_tile_base[mt];
    int n0 = blockIdx.y * BNT;

    extern __shared__ uint32_t sm2[];
    __shared__ int   s_toks[BMT];
    __shared__ float s_wts[BMT];

    int tid = threadIdx.x, lane = tid & 31, wid = tid >> 5;
    if (tid < BMT) {
        s_toks[tid] = g_row_tok[rb + tid];
        s_wts[tid]  = g_row_w[rb + tid];
    }
    __syncthreads();

    uint32_t sbase = smem_u32(sm2);
    const __half* dpe = g_dph + (size_t)e * DM * HID;   // [n][k]

    const __half* asrc[2]; const __half* bsrc[2]; uint32_t tdst[2];
#pragma unroll
    for (int j = 0; j < 2; j++) {
        int p = tid + 256 * j;
        int row = p >> 2, pc = p & 3;
        asrc[j] = g_H + (size_t)(rb + row) * HID + pc * 8;
        bsrc[j] = dpe + (size_t)(n0 + row) * HID + pc * 8;
        tdst[j] = (uint32_t)(row * TSTRIDE + pc * 4) * 4u;
    }

    float ca[2][8][4] = {};
    uint32_t a_off = (uint32_t)(((wid & 3) * 32 + (lane & 15)) * ROWB + (lane >> 4) * 16);
    uint32_t b_off = (uint32_t)(((wid >> 2) * 64 + ((lane >> 4) & 1) * 8 + (lane & 7)) * ROWB
                                + ((lane >> 3) & 1) * 16);

    const int NC = HID / BK;   // 16
#pragma unroll
    for (int pc = 0; pc < S2 - 1; pc++) {
        uint32_t stg = sbase + (uint32_t)(pc * F2_STAGE * 4);
        int k0 = pc * BK;
#pragma unroll
        for (int j = 0; j < 2; j++) {
            CP16(stg + tdst[j], asrc[j] + k0);
            CP16(stg + TILE_WORDS * 4 + tdst[j], bsrc[j] + k0);
        }
        CP_COMMIT();
    }

    for (int c = 0; c < NC; ++c) {
        CP_WAIT(S2 - 2);
        __syncthreads();
        int cn = c + S2 - 1;
        if (cn < NC) {
            int k0 = cn * BK;
            uint32_t stg = sbase + (uint32_t)((cn % S2) * F2_STAGE * 4);
#pragma unroll
            for (int j = 0; j < 2; j++) {
                CP16(stg + tdst[j], asrc[j] + k0);
                CP16(stg + TILE_WORDS * 4 + tdst[j], bsrc[j] + k0);
            }
        }
        CP_COMMIT();
        uint32_t Ab = sbase + (uint32_t)((c % S2) * F2_STAGE * 4);
        uint32_t Bb = Ab + TILE_WORDS * 4;
#pragma unroll
        for (int s = 0; s < 2; s++) {
            uint32_t so = (uint32_t)(s * 32);
            uint32_t a[2][4], bf[4][4];
#pragma unroll
            for (int mi = 0; mi < 2; mi++)
                ldsm4(a[mi], Ab + a_off + (uint32_t)(mi * 16 * ROWB) + so);
#pragma unroll
            for (int pi = 0; pi < 4; pi++)
                ldsm4(bf[pi], Bb + b_off + (uint32_t)(pi * 16 * ROWB) + so);
#pragma unroll
            for (int pi = 0; pi < 4; pi++) {
#pragma unroll
                for (int h = 0; h < 2; h++) {
                    int ni = 2 * pi + h;
                    mma16(ca[0][ni], a[0], bf[pi][2 * h], bf[pi][2 * h + 1]);
                    mma16(ca[1][ni], a[1], bf[pi][2 * h], bf[pi][2 * h + 1]);
                }
            }
        }
    }

    // epilogue: deterministic atomic combine
    const float* dpb = dp_b + e * DM;
    int lr = (wid & 3) * 32 + (lane >> 2);
    int cbase = (wid >> 2) * 64 + 2 * (lane & 3);
#pragma unroll
    for (int ni = 0; ni < 8; ni++) {
        int col = n0 + cbase + ni * 8;
        float b0v = dpb[col], b1v = dpb[col + 1];
#pragma unroll
        for (int mi = 0; mi < 2; mi++) {
            int l0 = lr + mi * 16;
            int t0 = s_toks[l0];
            if (t0 >= 0) {
                float w = s_wts[l0];
                atomicAdd(out + (size_t)t0 * DM + col,     w * (ca[mi][ni][0] + b0v));
                atomicAdd(out + (size_t)t0 * DM + col + 1, w * (ca[mi][ni][1] + b1v));
            }
            int t1 = s_toks[l0 + 8];
            if (t1 >= 0) {
                float w = s_wts[l0 + 8];
                atomicAdd(out + (size_t)t1 * DM + col,     w * (ca[mi][ni][2] + b0v));
                atomicAdd(out + (size_t)t1 * DM + col + 1, w * (ca[mi][ni][3] + b1v));
            }
        }
    }
}

// ---------------- launcher ----------------
extern "C" void kernel_launch(void* const* d_in, const int* in_sizes, int n_in,
                              void* d_out, int out_size) {
    const float* x   = (const float*)d_in[0];
    const float* gw  = (const float*)d_in[1];
    const float* gb  = (const float*)d_in[2];
    const float* gpw = (const float*)d_in[3];
    const float* gpb = (const float*)d_in[4];
    const float* upw = (const float*)d_in[5];
    const float* upb = (const float*)d_in[6];
    const float* dpw = (const float*)d_in[7];
    const float* dpb = (const float*)d_in[8];
    float* out = (float*)d_out;

    static int attr_done = 0;
    if (!attr_done) {
        cudaFuncSetAttribute(ffn1_mma, cudaFuncAttributeMaxDynamicSharedMemorySize,
                             F1_SMEM);
        cudaFuncSetAttribute(ffn2_mma, cudaFuncAttributeMaxDynamicSharedMemorySize,
                             F2_SMEM);
        attr_done = 1;
    }

    init_kernel<<<1, 32>>>();
    gate_kernel<<<(T_TOK * 32 + 255) / 256, 256>>>(x, gw, gb);
    scan_kernel<<<1, 1>>>();
    scatter_kernel<<<(T_TOK + 255) / 256, 256>>>();
    convert_weights<<<dim3(32, 32, 3 * NE), dim3(32, 8)>>>(gpw, upw, dpw);
    zero_kernel<<<1024, 256>>>(out, (long)out_size);
    aux_kernel<<<1, 32>>>(out, (long)out_size);

    ffn1_mma<<<dim3(MTILES, HID / BNT), 512, F1_SMEM>>>(gpb, upb);
    ffn2_mma<<<dim3(MTILES, DM / BNT), 256, F2_SMEM>>>(dpb, out);
}

// round 15
// speedup vs baseline: 4.0681x; 1.2620x over previous
#include <cuda_runtime.h>
#include <cuda_fp16.h>
#include <math.h>
#include <stdint.h>

// ---------------- problem constants ----------------
#define T_TOK 16384
#define DM    1024
#define HID   512
#define NE    16
#define TOPK  2

// ---------------- tiling ----------------
#define BMT 128
#define BNT 128
#define MTILES 272
#define PAD_ROWS (MTILES * BMT)

// ffn1: BK=64, 2 stages
#define BK1 64
#define T1STR 36                       // words per 64-half row (32 data + 4 pad)
#define T1ROWB (T1STR * 4)             // 144 B
#define T1W (128 * T1STR)              // 4608 words per 128x64-half tile
#define F1_STAGE (3 * T1W)             // A + G + U = 13824 words
#define S1 2
#define F1_SMEM (S1 * F1_STAGE * 4)    // 110592 B

// ffn2: BK=32, 3 stages (unchanged)
#define BK2 32
#define TSTRIDE 20
#define ROWB (TSTRIDE * 4)             // 80 B
#define TILE_WORDS (128 * TSTRIDE)     // 2560
#define F2_STAGE (2 * TILE_WORDS)      // 5120 words
#define S2 3
#define F2_SMEM (S2 * F2_STAGE * 4)    // 61440 B

// ---------------- static scratch ----------------
__device__ int   g_counts[NE];
__device__ int   g_cursor[NE];
__device__ int   g_off[NE];
__device__ int   g_tile_e[MTILES];
__device__ int   g_tile_base[MTILES];
__device__ int   g_tok_idx[T_TOK * TOPK];
__device__ float g_tok_w[T_TOK * TOPK];
__device__ int   g_row_tok[PAD_ROWS];
__device__ float g_row_w[PAD_ROWS];
__device__ __align__(16) __half g_Xh[(size_t)T_TOK * DM];
__device__ __align__(16) __half g_gph[(size_t)NE * HID * DM];   // [e][n][k]
__device__ __align__(16) __half g_uph[(size_t)NE * HID * DM];   // [e][n][k]
__device__ __align__(16) __half g_dph[(size_t)NE * DM * HID];   // [e][n][k]
__device__ __align__(16) __half g_H[(size_t)PAD_ROWS * HID];

// ---------------- helpers ----------------
__device__ __forceinline__ uint32_t smem_u32(const void* p) {
    uint32_t a;
    asm("{ .reg .u64 t; cvta.to.shared.u64 t, %1; cvt.u32.u64 %0, t; }" : "=r"(a) : "l"(p));
    return a;
}

__device__ __forceinline__ void mma16(float c[4], const uint32_t a[4],
                                      uint32_t b0, uint32_t b1) {
    asm volatile(
        "mma.sync.aligned.m16n8k16.row.col.f32.f16.f16.f32 "
        "{%0,%1,%2,%3}, {%4,%5,%6,%7}, {%8,%9}, {%0,%1,%2,%3};"
        : "+f"(c[0]), "+f"(c[1]), "+f"(c[2]), "+f"(c[3])
        : "r"(a[0]), "r"(a[1]), "r"(a[2]), "r"(a[3]), "r"(b0), "r"(b1));
}

__device__ __forceinline__ void ldsm4(uint32_t r[4], uint32_t addr) {
    asm volatile("ldmatrix.sync.aligned.m8n8.x4.shared.b16 {%0,%1,%2,%3}, [%4];"
                 : "=r"(r[0]), "=r"(r[1]), "=r"(r[2]), "=r"(r[3]) : "r"(addr));
}

#define CP16(dst, src) \
    asm volatile("cp.async.cg.shared.global [%0], [%1], 16;" :: "r"(dst), "l"(src))
#define CP16Z(dst, src, sz) \
    asm volatile("cp.async.cg.shared.global [%0], [%1], 16, %2;" :: "r"(dst), "l"(src), "r"(sz))
#define CP_COMMIT() asm volatile("cp.async.commit_group;" ::: "memory")
#define CP_WAIT(n)  asm volatile("cp.async.wait_group %0;" :: "n"(n) : "memory")

// ---------------- routing kernels ----------------
__global__ void init_kernel() {
    int i = threadIdx.x;
    if (i < NE) g_counts[i] = 0;
}

// gate + fused fp16 conversion of x. Vectorized: lane owns expert-quad q=lane&3
// and d-slice g=lane>>2; all gw loads are coalesced LDG.128.
__global__ void gate_kernel(const float* __restrict__ x,
                            const float* __restrict__ gw,
                            const float* __restrict__ gb) {
    int gid = blockIdx.x * blockDim.x + threadIdx.x;
    int t = gid >> 5, lane = gid & 31;
    if (t >= T_TOK) return;
    int q = lane & 3, g = lane >> 2;

    const float* xr = x + (size_t)t * DM;
    __half* xo = g_Xh + (size_t)t * DM;
    const float4* gw4 = (const float4*)gw;   // row d = 4 float4; index d*4 + q

    float4 acc = make_float4(0.f, 0.f, 0.f, 0.f);
#pragma unroll 4
    for (int it = 0; it < 32; it++) {
        int d = it * 32 + g * 4;
        float4 x4 = *(const float4*)(xr + d);
        if (q == 0) {
            half2 a = __floats2half2_rn(x4.x, x4.y);
            half2 b = __floats2half2_rn(x4.z, x4.w);
            uint2 pk = make_uint2(*reinterpret_cast<uint32_t*>(&a),
                                  *reinterpret_cast<uint32_t*>(&b));
            *(uint2*)(xo + d) = pk;
        }
#pragma unroll
        for (int i = 0; i < 4; i++) {
            float4 w4 = gw4[(size_t)(d + i) * 4 + q];
            float xv = (&x4.x)[i];
            acc.x = fmaf(xv, w4.x, acc.x);
            acc.y = fmaf(xv, w4.y, acc.y);
            acc.z = fmaf(xv, w4.z, acc.z);
            acc.w = fmaf(xv, w4.w, acc.w);
        }
    }
    // reduce over the 8 d-slices (lanes differing in bits 2..4)
#pragma unroll
    for (int off = 4; off < 32; off <<= 1) {
        acc.x += __shfl_xor_sync(0xffffffffu, acc.x, off);
        acc.y += __shfl_xor_sync(0xffffffffu, acc.y, off);
        acc.z += __shfl_xor_sync(0xffffffffu, acc.z, off);
        acc.w += __shfl_xor_sync(0xffffffffu, acc.w, off);
    }
    // gather all 16 logits (lanes 0..3 hold quads 0..3)
    float s[NE];
#pragma unroll
    for (int src = 0; src < 4; src++) {
        s[src * 4 + 0] = __shfl_sync(0xffffffffu, acc.x, src);
        s[src * 4 + 1] = __shfl_sync(0xffffffffu, acc.y, src);
        s[src * 4 + 2] = __shfl_sync(0xffffffffu, acc.z, src);
        s[src * 4 + 3] = __shfl_sync(0xffffffffu, acc.w, src);
    }
    if (lane == 0) {
        float mx = -1e30f;
#pragma unroll
        for (int e = 0; e < NE; e++) { s[e] += gb[e]; mx = fmaxf(mx, s[e]); }
        float sum = 0.f;
#pragma unroll
        for (int e = 0; e < NE; e++) { s[e] = expf(s[e] - mx); sum += s[e]; }
        int i1 = 0; float v1 = -1.f;
#pragma unroll
        for (int e = 0; e < NE; e++) if (s[e] > v1) { v1 = s[e]; i1 = e; }
        int i2 = 0; float v2 = -1.f;
#pragma unroll
        for (int e = 0; e < NE; e++) if (e != i1 && s[e] > v2) { v2 = s[e]; i2 = e; }
        float p1 = v1 / sum, p2 = v2 / sum;
        float den = p1 + p2 + 1e-9f;
        g_tok_idx[2 * t + 0] = i1; g_tok_w[2 * t + 0] = p1 / den;
        g_tok_idx[2 * t + 1] = i2; g_tok_w[2 * t + 1] = p2 / den;
        atomicAdd(&g_counts[i1], 1);
        atomicAdd(&g_counts[i2], 1);
    }
}

__global__ void scan_kernel() {
    int off = 0, tile = 0;
    for (int e = 0; e < NE; e++) {
        g_off[e] = off; g_cursor[e] = 0;
        int c = g_counts[e];
        int nt = (c + BMT - 1) / BMT;
        for (int j = 0; j < nt; j++) {
            g_tile_e[tile] = e;
            g_tile_base[tile] = off + j * BMT;
            tile++;
        }
        for (int r = off + c; r < off + nt * BMT; r++) {
            g_row_tok[r] = -1;
            g_row_w[r] = 0.f;
        }
        off += nt * BMT;
    }
    for (; tile < MTILES; tile++) g_tile_e[tile] = -1;
}

__global__ void scatter_kernel() {
    int t = blockIdx.x * blockDim.x + threadIdx.x;
    if (t >= T_TOK) return;
#pragma unroll
    for (int k = 0; k < TOPK; k++) {
        int e = g_tok_idx[2 * t + k];
        int pos = g_off[e] + atomicAdd(&g_cursor[e], 1);
        g_row_tok[pos] = t;
        g_row_w[pos] = g_tok_w[2 * t + k];
    }
}

__global__ void zero_kernel(float* out, long n) {
    long i = blockIdx.x * (long)blockDim.x + threadIdx.x;
    long st = (long)gridDim.x * blockDim.x;
    for (; i < n; i += st) out[i] = 0.f;
}

__global__ void aux_kernel(float* out, long out_size) {
    if (blockIdx.x == 0 && threadIdx.x == 0) {
        const float cap = 1.25f * (float)(T_TOK * TOPK) / (float)NE;
        float sum = 0.f;
        for (int e = 0; e < NE; e++) {
            float l = (float)g_counts[e] - cap;
            if (l > 0.f) sum += l;
        }
        float aux = 0.01f * sum / (float)NE / (float)T_TOK;
        long TD = (long)T_TOK * DM;
        if (out_size > TD) out[TD] = aux;
    }
}

// all three weights: [e][K][N] float -> [e][N][K] half, one fused launch
__global__ void convert_weights(const float* __restrict__ gp,
                                const float* __restrict__ up,
                                const float* __restrict__ dp) {
    __shared__ float tile[32][33];
    int z = blockIdx.z;                // 0..3*NE-1
    const float* src; __half* dst; int K, N;
    if (z < NE)          { src = gp + (size_t)z * DM * HID;        dst = g_gph + (size_t)z * HID * DM;        K = DM;  N = HID; }
    else if (z < 2 * NE) { src = up + (size_t)(z - NE) * DM * HID; dst = g_uph + (size_t)(z - NE) * HID * DM; K = DM;  N = HID; }
    else                 { src = dp + (size_t)(z - 2 * NE) * HID * DM; dst = g_dph + (size_t)(z - 2 * NE) * DM * HID; K = HID; N = DM; }
    int k0 = blockIdx.y * 32, n0 = blockIdx.x * 32;
    if (k0 >= K || n0 >= N) return;
    int tx = threadIdx.x, ty = threadIdx.y;
#pragma unroll
    for (int i = 0; i < 32; i += 8)
        tile[ty + i][tx] = src[(size_t)(k0 + ty + i) * N + n0 + tx];
    __syncthreads();
#pragma unroll
    for (int i = 0; i < 32; i += 8)
        dst[(size_t)(n0 + ty + i) * K + k0 + tx] = __float2half_rn(tile[tx][ty + i]);
}

// ============ FFN stage 1: H = (X@gp + b) * silu(X@up + b) ============
// 512 threads, 16 warps in 4x4 layout, warp tile 32x32, BK=64, 2 stages
__global__ void __launch_bounds__(512, 1)
ffn1_mma(const float* __restrict__ gp_b, const float* __restrict__ up_b) {
    int mt = blockIdx.x;
    int e = g_tile_e[mt];
    if (e < 0) return;
    int rb = g_tile_base[mt];
    int n0 = blockIdx.y * BNT;

    extern __shared__ uint32_t sm[];
    __shared__ int s_toks[BMT];

    int tid = threadIdx.x, lane = tid & 31, wid = tid >> 5;
    int wm = wid & 3, wn = wid >> 2;   // 4x4 warp grid
    if (tid < BMT) s_toks[tid] = g_row_tok[rb + tid];
    __syncthreads();

    uint32_t sbase = smem_u32(sm);
    const __half* gpe = g_gph + (size_t)e * HID * DM;   // [n][k]
    const __half* upe = g_uph + (size_t)e * HID * DM;

    // loader mapping: 2 x 16B pieces per tile per thread (1024 pieces/tile)
    const __half* asrc[2]; uint32_t asz[2], tdst[2];
    const __half* gsrc[2]; const __half* usrc[2];
#pragma unroll
    for (int j = 0; j < 2; j++) {
        int p = tid + 512 * j;
        int row = p >> 3, pc = p & 7;
        int tok = s_toks[row];
        asrc[j] = g_Xh + (size_t)(tok >= 0 ? tok : 0) * DM + pc * 8;
        asz[j]  = (tok >= 0) ? 16u : 0u;
        gsrc[j] = gpe + (size_t)(n0 + row) * DM + pc * 8;
        usrc[j] = upe + (size_t)(n0 + row) * DM + pc * 8;
        tdst[j] = (uint32_t)(row * T1STR + pc * 4) * 4u;
    }

    float cg[2][4][4] = {}, cu[2][4][4] = {};
    uint32_t a_off = (uint32_t)((wm * 32 + (lane & 15)) * T1ROWB + (lane >> 4) * 16);
    uint32_t b_off = (uint32_t)((wn * 32 + ((lane >> 4) & 1) * 8 + (lane & 7)) * T1ROWB
                                + ((lane >> 3) & 1) * 16);

    const int NC = DM / BK1;   // 16
    // prologue: chunk 0
    {
#pragma unroll
        for (int j = 0; j < 2; j++) {
            CP16Z(sbase + tdst[j], asrc[j], asz[j]);
            CP16(sbase + T1W * 4 + tdst[j], gsrc[j]);
            CP16(sbase + 2 * T1W * 4 + tdst[j], usrc[j]);
        }
        CP_COMMIT();
    }

    for (int c = 0; c < NC; ++c) {
        CP_WAIT(0);
        __syncthreads();
        int cn = c + 1;
        if (cn < NC) {
            int k0 = cn * BK1;
            uint32_t stg = sbase + (uint32_t)((cn & 1) * F1_STAGE * 4);
#pragma unroll
            for (int j = 0; j < 2; j++) {
                CP16Z(stg + tdst[j], asrc[j] + k0, asz[j]);
                CP16(stg + T1W * 4 + tdst[j], gsrc[j] + k0);
                CP16(stg + 2 * T1W * 4 + tdst[j], usrc[j] + k0);
            }
        }
        CP_COMMIT();
        uint32_t Ab = sbase + (uint32_t)((c & 1) * F1_STAGE * 4);
        uint32_t Gb = Ab + T1W * 4;
        uint32_t Ub = Gb + T1W * 4;
#pragma unroll
        for (int s = 0; s < 4; s++) {          // four k16 slices per chunk
            uint32_t so = (uint32_t)(s * 32);  // 16 halves
            uint32_t a[2][4], gf[2][4], uf[2][4];
#pragma unroll
            for (int mi = 0; mi < 2; mi++)
                ldsm4(a[mi], Ab + a_off + (uint32_t)(mi * 16 * T1ROWB) + so);
#pragma unroll
            for (int pi = 0; pi < 2; pi++) {
                ldsm4(gf[pi], Gb + b_off + (uint32_t)(pi * 16 * T1ROWB) + so);
                ldsm4(uf[pi], Ub + b_off + (uint32_t)(pi * 16 * T1ROWB) + so);
            }
#pragma unroll
            for (int pi = 0; pi < 2; pi++) {
#pragma unroll
                for (int h = 0; h < 2; h++) {
                    int ni = 2 * pi + h;
                    uint32_t g0 = gf[pi][2 * h], g1 = gf[pi][2 * h + 1];
                    uint32_t u0 = uf[pi][2 * h], u1 = uf[pi][2 * h + 1];
                    mma16(cg[0][ni], a[0], g0, g1);
                    mma16(cg[1][ni], a[1], g0, g1);
                    mma16(cu[0][ni], a[0], u0, u1);
                    mma16(cu[1][ni], a[1], u0, u1);
                }
            }
        }
    }

    // epilogue: h = (g + gpb) * silu(u + upb) -> g_H (fp16)
    const float* gpb = gp_b + e * HID + n0;
    const float* upb = up_b + e * HID + n0;
    int rrow = rb + wm * 32 + (lane >> 2);
    int cbase = wn * 32 + 2 * (lane & 3);
#pragma unroll
    for (int ni = 0; ni < 4; ni++) {
        int col = cbase + ni * 8;
        float gb0 = gpb[col], gb1 = gpb[col + 1];
        float ub0 = upb[col], ub1 = upb[col + 1];
#pragma unroll
        for (int mi = 0; mi < 2; mi++) {
            int r0 = rrow + mi * 16;
            float g, u, h0, h1;
            g = cg[mi][ni][0] + gb0; u = cu[mi][ni][0] + ub0;
            h0 = g * (u / (1.f + expf(-u)));
            g = cg[mi][ni][1] + gb1; u = cu[mi][ni][1] + ub1;
            h1 = g * (u / (1.f + expf(-u)));
            *(half2*)(g_H + (size_t)r0 * HID + n0 + col) = __floats2half2_rn(h0, h1);
            g = cg[mi][ni][2] + gb0; u = cu[mi][ni][2] + ub0;
            h0 = g * (u / (1.f + expf(-u)));
            g = cg[mi][ni][3] + gb1; u = cu[mi][ni][3] + ub1;
            h1 = g * (u / (1.f + expf(-u)));
            *(half2*)(g_H + (size_t)(r0 + 8) * HID + n0 + col) = __floats2half2_rn(h0, h1);
        }
    }
}

// ============ FFN stage 2: out[tok] += w * (H @ dp_w + dp_b), fp16 mma ============
__global__ void __launch_bounds__(256, 2)
ffn2_mma(const float* __restrict__ dp_b, float* __restrict__ out) {
    int mt = blockIdx.x;
    int e = g_tile_e[mt];
    if (e < 0) return;
    int rb = g_tile_base[mt];
    int n0 = blockIdx.y * BNT;

    extern __shared__ uint32_t sm2[];
    __shared__ int   s_toks[BMT];
    __shared__ float s_wts[BMT];

    int tid = threadIdx.x, lane = tid & 31, wid = tid >> 5;
    if (tid < BMT) {
        s_toks[tid] = g_row_tok[rb + tid];
        s_wts[tid]  = g_row_w[rb + tid];
    }
    __syncthreads();

    uint32_t sbase = smem_u32(sm2);
    const __half* dpe = g_dph + (size_t)e * DM * HID;   // [n][k]

    const __half* asrc[2]; const __half* bsrc[2]; uint32_t tdst[2];
#pragma unroll
    for (int j = 0; j < 2; j++) {
        int p = tid + 256 * j;
        int row = p >> 2, pc = p & 3;
        asrc[j] = g_H + (size_t)(rb + row) * HID + pc * 8;
        bsrc[j] = dpe + (size_t)(n0 + row) * HID + pc * 8;
        tdst[j] = (uint32_t)(row * TSTRIDE + pc * 4) * 4u;
    }

    float ca[2][8][4] = {};
    uint32_t a_off = (uint32_t)(((wid & 3) * 32 + (lane & 15)) * ROWB + (lane >> 4) * 16);
    uint32_t b_off = (uint32_t)(((wid >> 2) * 64 + ((lane >> 4) & 1) * 8 + (lane & 7)) * ROWB
                                + ((lane >> 3) & 1) * 16);

    const int NC = HID / BK2;   // 16
#pragma unroll
    for (int pc = 0; pc < S2 - 1; pc++) {
        uint32_t stg = sbase + (uint32_t)(pc * F2_STAGE * 4);
        int k0 = pc * BK2;
#pragma unroll
        for (int j = 0; j < 2; j++) {
            CP16(stg + tdst[j], asrc[j] + k0);
            CP16(stg + TILE_WORDS * 4 + tdst[j], bsrc[j] + k0);
        }
        CP_COMMIT();
    }

    for (int c = 0; c < NC; ++c) {
        CP_WAIT(S2 - 2);
        __syncthreads();
        int cn = c + S2 - 1;
        if (cn < NC) {
            int k0 = cn * BK2;
            uint32_t stg = sbase + (uint32_t)((cn % S2) * F2_STAGE * 4);
#pragma unroll
            for (int j = 0; j < 2; j++) {
                CP16(stg + tdst[j], asrc[j] + k0);
                CP16(stg + TILE_WORDS * 4 + tdst[j], bsrc[j] + k0);
            }
        }
        CP_COMMIT();
        uint32_t Ab = sbase + (uint32_t)((c % S2) * F2_STAGE * 4);
        uint32_t Bb = Ab + TILE_WORDS * 4;
#pragma unroll
        for (int s = 0; s < 2; s++) {
            uint32_t so = (uint32_t)(s * 32);
            uint32_t a[2][4], bf[4][4];
#pragma unroll
            for (int mi = 0; mi < 2; mi++)
                ldsm4(a[mi], Ab + a_off + (uint32_t)(mi * 16 * ROWB) + so);
#pragma unroll
            for (int pi = 0; pi < 4; pi++)
                ldsm4(bf[pi], Bb + b_off + (uint32_t)(pi * 16 * ROWB) + so);
#pragma unroll
            for (int pi = 0; pi < 4; pi++) {
#pragma unroll
                for (int h = 0; h < 2; h++) {
                    int ni = 2 * pi + h;
                    mma16(ca[0][ni], a[0], bf[pi][2 * h], bf[pi][2 * h + 1]);
                    mma16(ca[1][ni], a[1], bf[pi][2 * h], bf[pi][2 * h + 1]);
                }
            }
        }
    }

    // epilogue: deterministic atomic combine
    const float* dpb = dp_b + e * DM;
    int lr = (wid & 3) * 32 + (lane >> 2);
    int cbase = (wid >> 2) * 64 + 2 * (lane & 3);
#pragma unroll
    for (int ni = 0; ni < 8; ni++) {
        int col = n0 + cbase + ni * 8;
        float b0v = dpb[col], b1v = dpb[col + 1];
#pragma unroll
        for (int mi = 0; mi < 2; mi++) {
            int l0 = lr + mi * 16;
            int t0 = s_toks[l0];
            if (t0 >= 0) {
                float w = s_wts[l0];
                atomicAdd(out + (size_t)t0 * DM + col,     w * (ca[mi][ni][0] + b0v));
                atomicAdd(out + (size_t)t0 * DM + col + 1, w * (ca[mi][ni][1] + b1v));
            }
            int t1 = s_toks[l0 + 8];
            if (t1 >= 0) {
                float w = s_wts[l0 + 8];
                atomicAdd(out + (size_t)t1 * DM + col,     w * (ca[mi][ni][2] + b0v));
                atomicAdd(out + (size_t)t1 * DM + col + 1, w * (ca[mi][ni][3] + b1v));
            }
        }
    }
}

// ---------------- launcher ----------------
extern "C" void kernel_launch(void* const* d_in, const int* in_sizes, int n_in,
                              void* d_out, int out_size) {
    const float* x   = (const float*)d_in[0];
    const float* gw  = (const float*)d_in[1];
    const float* gb  = (const float*)d_in[2];
    const float* gpw = (const float*)d_in[3];
    const float* gpb = (const float*)d_in[4];
    const float* upw = (const float*)d_in[5];
    const float* upb = (const float*)d_in[6];
    const float* dpw = (const float*)d_in[7];
    const float* dpb = (const float*)d_in[8];
    float* out = (float*)d_out;

    static int attr_done = 0;
    if (!attr_done) {
        cudaFuncSetAttribute(ffn1_mma, cudaFuncAttributeMaxDynamicSharedMemorySize,
                             F1_SMEM);
        cudaFuncSetAttribute(ffn2_mma, cudaFuncAttributeMaxDynamicSharedMemorySize,
                             F2_SMEM);
        attr_done = 1;
    }

    init_kernel<<<1, 32>>>();
    gate_kernel<<<(T_TOK * 32 + 255) / 256, 256>>>(x, gw, gb);
    scan_kernel<<<1, 1>>>();
    scatter_kernel<<<(T_TOK + 255) / 256, 256>>>();
    convert_weights<<<dim3(32, 32, 3 * NE), dim3(32, 8)>>>(gpw, upw, dpw);
    zero_kernel<<<1024, 256>>>(out, (long)out_size);
    aux_kernel<<<1, 32>>>(out, (long)out_size);

    ffn1_mma<<<dim3(MTILES, HID / BNT), 512, F1_SMEM>>>(gpb, upb);
    ffn2_mma<<<dim3(MTILES, DM / BNT), 256, F2_SMEM>>>(dpb, out);
}

// round 16
// speedup vs baseline: 5.7947x; 1.4244x over previous
#include <cuda_runtime.h>
#include <cuda_fp16.h>
#include <math.h>
#include <stdint.h>

// ---------------- problem constants ----------------
#define T_TOK 16384
#define DM    1024
#define HID   512
#define NE    16
#define TOPK  2

// ---------------- tiling ----------------
#define BMT 128
#define BNT 128
#define MTILES 272
#define PAD_ROWS (MTILES * BMT)

// shared tile geometry (BK=64, 2 stages) for both FFN kernels
#define BK1 64
#define T1STR 36                       // words per 64-half row (32 data + 4 pad)
#define T1ROWB (T1STR * 4)             // 144 B
#define T1W (128 * T1STR)              // 4608 words per 128x64-half tile
#define F1_STAGE (3 * T1W)             // A + G + U
#define F2_STAGE (2 * T1W)             // A + B
#define F1_SMEM (2 * F1_STAGE * 4)     // 110592 B
#define F2_SMEM (2 * F2_STAGE * 4)     // 73728 B

// ---------------- static scratch ----------------
__device__ int   g_counts[NE];
__device__ int   g_cursor[NE];
__device__ int   g_off[NE];
__device__ int   g_tile_e[MTILES];
__device__ int   g_tile_base[MTILES];
__device__ int   g_tok_idx[T_TOK * TOPK];
__device__ float g_tok_w[T_TOK * TOPK];
__device__ int   g_row_tok[PAD_ROWS];
__device__ float g_row_w[PAD_ROWS];
__device__ __align__(16) __half g_Xh[(size_t)T_TOK * DM];
__device__ __align__(16) __half g_gph[(size_t)NE * HID * DM];   // [e][n][k]
__device__ __align__(16) __half g_uph[(size_t)NE * HID * DM];   // [e][n][k]
__device__ __align__(16) __half g_dph[(size_t)NE * DM * HID];   // [e][n][k]
__device__ __align__(16) __half g_H[(size_t)PAD_ROWS * HID];

// ---------------- helpers ----------------
__device__ __forceinline__ uint32_t smem_u32(const void* p) {
    uint32_t a;
    asm("{ .reg .u64 t; cvta.to.shared.u64 t, %1; cvt.u32.u64 %0, t; }" : "=r"(a) : "l"(p));
    return a;
}

__device__ __forceinline__ void mma16(float c[4], const uint32_t a[4],
                                      uint32_t b0, uint32_t b1) {
    asm volatile(
        "mma.sync.aligned.m16n8k16.row.col.f32.f16.f16.f32 "
        "{%0,%1,%2,%3}, {%4,%5,%6,%7}, {%8,%9}, {%0,%1,%2,%3};"
        : "+f"(c[0]), "+f"(c[1]), "+f"(c[2]), "+f"(c[3])
        : "r"(a[0]), "r"(a[1]), "r"(a[2]), "r"(a[3]), "r"(b0), "r"(b1));
}

__device__ __forceinline__ void ldsm4(uint32_t r[4], uint32_t addr) {
    asm volatile("ldmatrix.sync.aligned.m8n8.x4.shared.b16 {%0,%1,%2,%3}, [%4];"
                 : "=r"(r[0]), "=r"(r[1]), "=r"(r[2]), "=r"(r[3]) : "r"(addr));
}

#define CP16(dst, src) \
    asm volatile("cp.async.cg.shared.global [%0], [%1], 16;" :: "r"(dst), "l"(src))
#define CP16Z(dst, src, sz) \
    asm volatile("cp.async.cg.shared.global [%0], [%1], 16, %2;" :: "r"(dst), "l"(src), "r"(sz))
#define CP_COMMIT() asm volatile("cp.async.commit_group;" ::: "memory")
#define CP_WAIT(n)  asm volatile("cp.async.wait_group %0;" :: "n"(n) : "memory")

// ---------------- routing kernels ----------------
__global__ void init_kernel() {
    int i = threadIdx.x;
    if (i < NE) g_counts[i] = 0;
}

// gate + fused fp16 conversion of x; all gw loads coalesced LDG.128
__global__ void gate_kernel(const float* __restrict__ x,
                            const float* __restrict__ gw,
                            const float* __restrict__ gb) {
    int gid = blockIdx.x * blockDim.x + threadIdx.x;
    int t = gid >> 5, lane = gid & 31;
    if (t >= T_TOK) return;
    int q = lane & 3, g = lane >> 2;

    const float* xr = x + (size_t)t * DM;
    __half* xo = g_Xh + (size_t)t * DM;
    const float4* gw4 = (const float4*)gw;

    float4 acc = make_float4(0.f, 0.f, 0.f, 0.f);
#pragma unroll 4
    for (int it = 0; it < 32; it++) {
        int d = it * 32 + g * 4;
        float4 x4 = *(const float4*)(xr + d);
        if (q == 0) {
            half2 a = __floats2half2_rn(x4.x, x4.y);
            half2 b = __floats2half2_rn(x4.z, x4.w);
            uint2 pk = make_uint2(*reinterpret_cast<uint32_t*>(&a),
                                  *reinterpret_cast<uint32_t*>(&b));
            *(uint2*)(xo + d) = pk;
        }
#pragma unroll
        for (int i = 0; i < 4; i++) {
            float4 w4 = gw4[(size_t)(d + i) * 4 + q];
            float xv = (&x4.x)[i];
            acc.x = fmaf(xv, w4.x, acc.x);
            acc.y = fmaf(xv, w4.y, acc.y);
            acc.z = fmaf(xv, w4.z, acc.z);
            acc.w = fmaf(xv, w4.w, acc.w);
        }
    }
#pragma unroll
    for (int off = 4; off < 32; off <<= 1) {
        acc.x += __shfl_xor_sync(0xffffffffu, acc.x, off);
        acc.y += __shfl_xor_sync(0xffffffffu, acc.y, off);
        acc.z += __shfl_xor_sync(0xffffffffu, acc.z, off);
        acc.w += __shfl_xor_sync(0xffffffffu, acc.w, off);
    }
    float s[NE];
#pragma unroll
    for (int src = 0; src < 4; src++) {
        s[src * 4 + 0] = __shfl_sync(0xffffffffu, acc.x, src);
        s[src * 4 + 1] = __shfl_sync(0xffffffffu, acc.y, src);
        s[src * 4 + 2] = __shfl_sync(0xffffffffu, acc.z, src);
        s[src * 4 + 3] = __shfl_sync(0xffffffffu, acc.w, src);
    }
    if (lane == 0) {
        float mx = -1e30f;
#pragma unroll
        for (int e = 0; e < NE; e++) { s[e] += gb[e]; mx = fmaxf(mx, s[e]); }
        float sum = 0.f;
#pragma unroll
        for (int e = 0; e < NE; e++) { s[e] = expf(s[e] - mx); sum += s[e]; }
        int i1 = 0; float v1 = -1.f;
#pragma unroll
        for (int e = 0; e < NE; e++) if (s[e] > v1) { v1 = s[e]; i1 = e; }
        int i2 = 0; float v2 = -1.f;
#pragma unroll
        for (int e = 0; e < NE; e++) if (e != i1 && s[e] > v2) { v2 = s[e]; i2 = e; }
        float p1 = v1 / sum, p2 = v2 / sum;
        float den = p1 + p2 + 1e-9f;
        g_tok_idx[2 * t + 0] = i1; g_tok_w[2 * t + 0] = p1 / den;
        g_tok_idx[2 * t + 1] = i2; g_tok_w[2 * t + 1] = p2 / den;
        atomicAdd(&g_counts[i1], 1);
        atomicAdd(&g_counts[i2], 1);
    }
}

// serial offsets + tile table only (padding fill moved to pad_kernel)
__global__ void scan_kernel() {
    int off = 0, tile = 0;
    for (int e = 0; e < NE; e++) {
        g_off[e] = off; g_cursor[e] = 0;
        int c = g_counts[e];
        int nt = (c + BMT - 1) / BMT;
        for (int j = 0; j < nt; j++) {
            g_tile_e[tile] = e;
            g_tile_base[tile] = off + j * BMT;
            tile++;
        }
        off += nt * BMT;
    }
    for (; tile < MTILES; tile++) g_tile_e[tile] = -1;
}

// parallel padding fill
__global__ void pad_kernel() {
    int r = blockIdx.x * blockDim.x + threadIdx.x;
    if (r >= PAD_ROWS) return;
#pragma unroll
    for (int e = 0; e < NE; e++) {
        int o = g_off[e];
        int c = g_counts[e];
        int end = o + ((c + BMT - 1) / BMT) * BMT;
        if (r >= o + c && r < end) {
            g_row_tok[r] = -1;
            g_row_w[r] = 0.f;
            return;
        }
    }
}

__global__ void scatter_kernel() {
    int t = blockIdx.x * blockDim.x + threadIdx.x;
    if (t >= T_TOK) return;
#pragma unroll
    for (int k = 0; k < TOPK; k++) {
        int e = g_tok_idx[2 * t + k];
        int pos = g_off[e] + atomicAdd(&g_cursor[e], 1);
        g_row_tok[pos] = t;
        g_row_w[pos] = g_tok_w[2 * t + k];
    }
}

__global__ void zero_kernel(float* out, long n) {
    long i = blockIdx.x * (long)blockDim.x + threadIdx.x;
    long st = (long)gridDim.x * blockDim.x;
    for (; i < n; i += st) out[i] = 0.f;
}

__global__ void aux_kernel(float* out, long out_size) {
    if (blockIdx.x == 0 && threadIdx.x == 0) {
        const float cap = 1.25f * (float)(T_TOK * TOPK) / (float)NE;
        float sum = 0.f;
        for (int e = 0; e < NE; e++) {
            float l = (float)g_counts[e] - cap;
            if (l > 0.f) sum += l;
        }
        float aux = 0.01f * sum / (float)NE / (float)T_TOK;
        long TD = (long)T_TOK * DM;
        if (out_size > TD) out[TD] = aux;
    }
}

// all three weights: [e][K][N] float -> [e][N][K] half
__global__ void convert_weights(const float* __restrict__ gp,
                                const float* __restrict__ up,
                                const float* __restrict__ dp) {
    __shared__ float tile[32][33];
    int z = blockIdx.z;
    const float* src; __half* dst; int K, N;
    if (z < NE)          { src = gp + (size_t)z * DM * HID;        dst = g_gph + (size_t)z * HID * DM;        K = DM;  N = HID; }
    else if (z < 2 * NE) { src = up + (size_t)(z - NE) * DM * HID; dst = g_uph + (size_t)(z - NE) * HID * DM; K = DM;  N = HID; }
    else                 { src = dp + (size_t)(z - 2 * NE) * HID * DM; dst = g_dph + (size_t)(z - 2 * NE) * DM * HID; K = HID; N = DM; }
    int k0 = blockIdx.y * 32, n0 = blockIdx.x * 32;
    if (k0 >= K || n0 >= N) return;
    int tx = threadIdx.x, ty = threadIdx.y;
#pragma unroll
    for (int i = 0; i < 32; i += 8)
        tile[ty + i][tx] = src[(size_t)(k0 + ty + i) * N + n0 + tx];
    __syncthreads();
#pragma unroll
    for (int i = 0; i < 32; i += 8)
        dst[(size_t)(n0 + ty + i) * K + k0 + tx] = __float2half_rn(tile[tx][ty + i]);
}

// ============ FFN stage 1: H = (X@gp + b) * silu(X@up + b) ============
__global__ void __launch_bounds__(512, 1)
ffn1_mma(const float* __restrict__ gp_b, const float* __restrict__ up_b) {
    int mt = blockIdx.x;
    int e = g_tile_e[mt];
    if (e < 0) return;
    int rb = g_tile_base[mt];
    int n0 = blockIdx.y * BNT;

    extern __shared__ uint32_t sm[];
    __shared__ int s_toks[BMT];

    int tid = threadIdx.x, lane = tid & 31, wid = tid >> 5;
    int wm = wid & 3, wn = wid >> 2;
    if (tid < BMT) s_toks[tid] = g_row_tok[rb + tid];
    __syncthreads();

    uint32_t sbase = smem_u32(sm);
    const __half* gpe = g_gph + (size_t)e * HID * DM;
    const __half* upe = g_uph + (size_t)e * HID * DM;

    const __half* asrc[2]; uint32_t asz[2], tdst[2];
    const __half* gsrc[2]; const __half* usrc[2];
#pragma unroll
    for (int j = 0; j < 2; j++) {
        int p = tid + 512 * j;
        int row = p >> 3, pc = p & 7;
        int tok = s_toks[row];
        asrc[j] = g_Xh + (size_t)(tok >= 0 ? tok : 0) * DM + pc * 8;
        asz[j]  = (tok >= 0) ? 16u : 0u;
        gsrc[j] = gpe + (size_t)(n0 + row) * DM + pc * 8;
        usrc[j] = upe + (size_t)(n0 + row) * DM + pc * 8;
        tdst[j] = (uint32_t)(row * T1STR + pc * 4) * 4u;
    }

    float cg[2][4][4] = {}, cu[2][4][4] = {};
    uint32_t a_off = (uint32_t)((wm * 32 + (lane & 15)) * T1ROWB + (lane >> 4) * 16);
    uint32_t b_off = (uint32_t)((wn * 32 + ((lane >> 4) & 1) * 8 + (lane & 7)) * T1ROWB
                                + ((lane >> 3) & 1) * 16);

    const int NC = DM / BK1;   // 16
    {
#pragma unroll
        for (int j = 0; j < 2; j++) {
            CP16Z(sbase + tdst[j], asrc[j], asz[j]);
            CP16(sbase + T1W * 4 + tdst[j], gsrc[j]);
            CP16(sbase + 2 * T1W * 4 + tdst[j], usrc[j]);
        }
        CP_COMMIT();
    }

    for (int c = 0; c < NC; ++c) {
        CP_WAIT(0);
        __syncthreads();
        int cn = c + 1;
        if (cn < NC) {
            int k0 = cn * BK1;
            uint32_t stg = sbase + (uint32_t)((cn & 1) * F1_STAGE * 4);
#pragma unroll
            for (int j = 0; j < 2; j++) {
                CP16Z(stg + tdst[j], asrc[j] + k0, asz[j]);
                CP16(stg + T1W * 4 + tdst[j], gsrc[j] + k0);
                CP16(stg + 2 * T1W * 4 + tdst[j], usrc[j] + k0);
            }
        }
        CP_COMMIT();
        uint32_t Ab = sbase + (uint32_t)((c & 1) * F1_STAGE * 4);
        uint32_t Gb = Ab + T1W * 4;
        uint32_t Ub = Gb + T1W * 4;
#pragma unroll
        for (int s = 0; s < 4; s++) {
            uint32_t so = (uint32_t)(s * 32);
            uint32_t a[2][4], gf[2][4], uf[2][4];
#pragma unroll
            for (int mi = 0; mi < 2; mi++)
                ldsm4(a[mi], Ab + a_off + (uint32_t)(mi * 16 * T1ROWB) + so);
#pragma unroll
            for (int pi = 0; pi < 2; pi++) {
                ldsm4(gf[pi], Gb + b_off + (uint32_t)(pi * 16 * T1ROWB) + so);
                ldsm4(uf[pi], Ub + b_off + (uint32_t)(pi * 16 * T1ROWB) + so);
            }
#pragma unroll
            for (int pi = 0; pi < 2; pi++) {
#pragma unroll
                for (int h = 0; h < 2; h++) {
                    int ni = 2 * pi + h;
                    uint32_t g0 = gf[pi][2 * h], g1 = gf[pi][2 * h + 1];
                    uint32_t u0 = uf[pi][2 * h], u1 = uf[pi][2 * h + 1];
                    mma16(cg[0][ni], a[0], g0, g1);
                    mma16(cg[1][ni], a[1], g0, g1);
                    mma16(cu[0][ni], a[0], u0, u1);
                    mma16(cu[1][ni], a[1], u0, u1);
                }
            }
        }
    }

    const float* gpb = gp_b + e * HID + n0;
    const float* upb = up_b + e * HID + n0;
    int rrow = rb + wm * 32 + (lane >> 2);
    int cbase = wn * 32 + 2 * (lane & 3);
#pragma unroll
    for (int ni = 0; ni < 4; ni++) {
        int col = cbase + ni * 8;
        float gb0 = gpb[col], gb1 = gpb[col + 1];
        float ub0 = upb[col], ub1 = upb[col + 1];
#pragma unroll
        for (int mi = 0; mi < 2; mi++) {
            int r0 = rrow + mi * 16;
            float g, u, h0, h1;
            g = cg[mi][ni][0] + gb0; u = cu[mi][ni][0] + ub0;
            h0 = g * (u / (1.f + expf(-u)));
            g = cg[mi][ni][1] + gb1; u = cu[mi][ni][1] + ub1;
            h1 = g * (u / (1.f + expf(-u)));
            *(half2*)(g_H + (size_t)r0 * HID + n0 + col) = __floats2half2_rn(h0, h1);
            g = cg[mi][ni][2] + gb0; u = cu[mi][ni][2] + ub0;
            h0 = g * (u / (1.f + expf(-u)));
            g = cg[mi][ni][3] + gb1; u = cu[mi][ni][3] + ub1;
            h1 = g * (u / (1.f + expf(-u)));
            *(half2*)(g_H + (size_t)(r0 + 8) * HID + n0 + col) = __floats2half2_rn(h0, h1);
        }
    }
}

// ============ FFN stage 2: out[tok] += w * (H @ dp_w + dp_b) ============
// 512 threads, 4x4 warps, warp tile 32x32, BK=64, 2 stages
__global__ void __launch_bounds__(512, 1)
ffn2_mma(const float* __restrict__ dp_b, float* __restrict__ out) {
    int mt = blockIdx.x;
    int e = g_tile_e[mt];
    if (e < 0) return;
    int rb = g_tile_base[mt];
    int n0 = blockIdx.y * BNT;

    extern __shared__ uint32_t sm2[];
    __shared__ int   s_toks[BMT];
    __shared__ float s_wts[BMT];

    int tid = threadIdx.x, lane = tid & 31, wid = tid >> 5;
    int wm = wid & 3, wn = wid >> 2;
    if (tid < BMT) {
        s_toks[tid] = g_row_tok[rb + tid];
        s_wts[tid]  = g_row_w[rb + tid];
    }
    __syncthreads();

    uint32_t sbase = smem_u32(sm2);
    const __half* dpe = g_dph + (size_t)e * DM * HID;   // [n][k]

    const __half* asrc[2]; const __half* bsrc[2]; uint32_t tdst[2];
#pragma unroll
    for (int j = 0; j < 2; j++) {
        int p = tid + 512 * j;
        int row = p >> 3, pc = p & 7;
        asrc[j] = g_H + (size_t)(rb + row) * HID + pc * 8;
        bsrc[j] = dpe + (size_t)(n0 + row) * HID + pc * 8;
        tdst[j] = (uint32_t)(row * T1STR + pc * 4) * 4u;
    }

    float ca[2][4][4] = {};
    uint32_t a_off = (uint32_t)((wm * 32 + (lane & 15)) * T1ROWB + (lane >> 4) * 16);
    uint32_t b_off = (uint32_t)((wn * 32 + ((lane >> 4) & 1) * 8 + (lane & 7)) * T1ROWB
                                + ((lane >> 3) & 1) * 16);

    const int NC = HID / BK1;   // 8
    {
#pragma unroll
        for (int j = 0; j < 2; j++) {
            CP16(sbase + tdst[j], asrc[j]);
            CP16(sbase + T1W * 4 + tdst[j], bsrc[j]);
        }
        CP_COMMIT();
    }

    for (int c = 0; c < NC; ++c) {
        CP_WAIT(0);
        __syncthreads();
        int cn = c + 1;
        if (cn < NC) {
            int k0 = cn * BK1;
            uint32_t stg = sbase + (uint32_t)((cn & 1) * F2_STAGE * 4);
#pragma unroll
            for (int j = 0; j < 2; j++) {
                CP16(stg + tdst[j], asrc[j] + k0);
                CP16(stg + T1W * 4 + tdst[j], bsrc[j] + k0);
            }
        }
        CP_COMMIT();
        uint32_t Ab = sbase + (uint32_t)((c & 1) * F2_STAGE * 4);
        uint32_t Bb = Ab + T1W * 4;
#pragma unroll
        for (int s = 0; s < 4; s++) {
            uint32_t so = (uint32_t)(s * 32);
            uint32_t a[2][4], bf[2][4];
#pragma unroll
            for (int mi = 0; mi < 2; mi++)
                ldsm4(a[mi], Ab + a_off + (uint32_t)(mi * 16 * T1ROWB) + so);
#pragma unroll
            for (int pi = 0; pi < 2; pi++)
                ldsm4(bf[pi], Bb + b_off + (uint32_t)(pi * 16 * T1ROWB) + so);
#pragma unroll
            for (int pi = 0; pi < 2; pi++) {
#pragma unroll
                for (int h = 0; h < 2; h++) {
                    int ni = 2 * pi + h;
                    mma16(ca[0][ni], a[0], bf[pi][2 * h], bf[pi][2 * h + 1]);
                    mma16(ca[1][ni], a[1], bf[pi][2 * h], bf[pi][2 * h + 1]);
                }
            }
        }
    }

    // epilogue: deterministic atomic combine
    const float* dpb = dp_b + e * DM;
    int lr = wm * 32 + (lane >> 2);
    int cbase = wn * 32 + 2 * (lane & 3);
#pragma unroll
    for (int ni = 0; ni < 4; ni++) {
        int col = n0 + cbase + ni * 8;
        float b0v = dpb[col], b1v = dpb[col + 1];
#pragma unroll
        for (int mi = 0; mi < 2; mi++) {
            int l0 = lr + mi * 16;
            int t0 = s_toks[l0];
            if (t0 >= 0) {
                float w = s_wts[l0];
                atomicAdd(out + (size_t)t0 * DM + col,     w * (ca[mi][ni][0] + b0v));
                atomicAdd(out + (size_t)t0 * DM + col + 1, w * (ca[mi][ni][1] + b1v));
            }
            int t1 = s_toks[l0 + 8];
            if (t1 >= 0) {
                float w = s_wts[l0 + 8];
                atomicAdd(out + (size_t)t1 * DM + col,     w * (ca[mi][ni][2] + b0v));
                atomicAdd(out + (size_t)t1 * DM + col + 1, w * (ca[mi][ni][3] + b1v));
            }
        }
    }
}

// ---------------- launcher ----------------
extern "C" void kernel_launch(void* const* d_in, const int* in_sizes, int n_in,
                              void* d_out, int out_size) {
    const float* x   = (const float*)d_in[0];
    const float* gw  = (const float*)d_in[1];
    const float* gb  = (const float*)d_in[2];
    const float* gpw = (const float*)d_in[3];
    const float* gpb = (const float*)d_in[4];
    const float* upw = (const float*)d_in[5];
    const float* upb = (const float*)d_in[6];
    const float* dpw = (const float*)d_in[7];
    const float* dpb = (const float*)d_in[8];
    float* out = (float*)d_out;

    static int init_done = 0;
    static cudaStream_t s2;
    static cudaEvent_t ev_fork, ev_join;
    if (!init_done) {
        cudaFuncSetAttribute(ffn1_mma, cudaFuncAttributeMaxDynamicSharedMemorySize,
                             F1_SMEM);
        cudaFuncSetAttribute(ffn2_mma, cudaFuncAttributeMaxDynamicSharedMemorySize,
                             F2_SMEM);
        cudaStreamCreateWithFlags(&s2, cudaStreamNonBlocking);
        cudaEventCreateWithFlags(&ev_fork, cudaEventDisableTiming);
        cudaEventCreateWithFlags(&ev_join, cudaEventDisableTiming);
        init_done = 1;
    }

    // fork: weight conversion + output zeroing run concurrently with routing
    cudaEventRecord(ev_fork, 0);
    cudaStreamWaitEvent(s2, ev_fork, 0);
    convert_weights<<<dim3(32, 32, 3 * NE), dim3(32, 8), 0, s2>>>(gpw, upw, dpw);
    zero_kernel<<<1024, 256, 0, s2>>>(out, (long)out_size);
    cudaEventRecord(ev_join, s2);

    // main: routing chain
    init_kernel<<<1, 32>>>();
    gate_kernel<<<(T_TOK * 32 + 255) / 256, 256>>>(x, gw, gb);
    scan_kernel<<<1, 1>>>();
    scatter_kernel<<<(T_TOK + 255) / 256, 256>>>();
    pad_kernel<<<(PAD_ROWS + 255) / 256, 256>>>();

    // join, then aux (writes out[TD], must follow zero) and FFN
    cudaStreamWaitEvent(0, ev_join, 0);
    aux_kernel<<<1, 32>>>(out, (long)out_size);

    ffn1_mma<<<dim3(MTILES, HID / BNT), 512, F1_SMEM>>>(gpb, upb);
    ffn2_mma<<<dim3(MTILES, DM / BNT), 512, F2_SMEM>>>(dpb, out);
}